// round 2
// baseline (speedup 1.0000x reference)
#include <cuda_runtime.h>
#include <math.h>

#define M_ROWS 65536
#define B_ROWS 2048
#define D_IN   13
#define H1N    300
#define H2N    600
#define H3N    100
#define TILE_M 32
#define NTHREADS 256
#define EPS_F  1e-8f
#define SCALE_F 23.0f
#define SLOPE  0.01f

// ---- shared memory layout (float offsets) ----
#define OFF_H2T   0                      // [600][36] = 21600
#define OFF_SW    21600                  // max(300*65, 600*33, 100*16) = 19800
#define OFF_H1T   41400                  // [300][36] = 10800 (h3T aliases here: [100][36])
#define OFF_SXT   52200                  // [13][36] -> reserve 576
#define OFF_T1    52776                  // [32][13] = 416
#define OFF_RINV  53192                  // 32
#define SMEM_FLOATS 53224                // 212896 bytes

__device__ float        g_vn[B_ROWS * D_IN];
__device__ unsigned int g_umax[B_ROWS];

__device__ __forceinline__ unsigned fkey(float f) {
    unsigned b = __float_as_uint(f);
    return (b & 0x80000000u) ? ~b : (b | 0x80000000u);
}
__device__ __forceinline__ float funkey(unsigned u) {
    unsigned b = (u & 0x80000000u) ? (u ^ 0x80000000u) : ~u;
    return __uint_as_float(b);
}

// ---------- kernel 0: normalize value rows, reset maxes ----------
__global__ void prep_kernel(const float* __restrict__ value) {
    int t = blockIdx.x * blockDim.x + threadIdx.x;
    if (t < B_ROWS) {
        float v[D_IN];
        float s = 0.f;
        #pragma unroll
        for (int o = 0; o < D_IN; o++) { v[o] = value[t * D_IN + o]; s += v[o] * v[o]; }
        float inv = 1.f / fmaxf(sqrtf(s), EPS_F);
        #pragma unroll
        for (int o = 0; o < D_IN; o++) g_vn[t * D_IN + o] = v[o] * inv;
        g_umax[t] = 0u;
    }
}

// ---------- kernel 1: fused MLP + normalize + partial max-sim ----------
__global__ void __launch_bounds__(NTHREADS, 1)
mlp_sim_kernel(const float* __restrict__ memx,
               const float* __restrict__ W1, const float* __restrict__ b1,
               const float* __restrict__ W2, const float* __restrict__ b2,
               const float* __restrict__ W3, const float* __restrict__ b3,
               const float* __restrict__ W4, const float* __restrict__ b4)
{
    extern __shared__ float smem[];
    float* h2T  = smem + OFF_H2T;   // [600][36]
    float* sW   = smem + OFF_SW;
    float* h1T  = smem + OFF_H1T;   // [300][36]
    float* h3T  = smem + OFF_H1T;   // alias (h1 dead by layer 3)
    float* sxT  = smem + OFF_SXT;   // [13][36]
    float* t1   = smem + OFF_T1;    // [32][13]
    float* rinv = smem + OFF_RINV;  // [32]

    const int tid = threadIdx.x;
    const int tx  = tid & 31;
    const int ty  = tid >> 5;
    const int r0  = ty * 4;
    const int m0  = blockIdx.x * TILE_M;

    // ---- load x tile transposed ----
    for (int i = tid; i < TILE_M * D_IN; i += NTHREADS) {
        int r = i / D_IN, k = i - r * D_IN;
        sxT[k * 36 + r] = memx[(m0 + r) * D_IN + k];
    }
    __syncthreads();

    // ---- Layer 1: 13 -> 300, relu.  h1T[o][r] ----
    for (int i = tid; i < TILE_M * H1N; i += NTHREADS) {
        int r = i & (TILE_M - 1), o = i >> 5;
        float acc = b1[o];
        #pragma unroll
        for (int k = 0; k < D_IN; k++)
            acc += sxT[k * 36 + r] * W1[o * D_IN + k];
        h1T[o * 36 + r] = fmaxf(acc, 0.f);
    }
    __syncthreads();

    // ---- Layer 2: 300 -> 600, leaky.  chunks of 64 out-cols ----
    for (int oc = 0; oc < H2N; oc += 64) {
        // stage transposed weights sW[k][c], zero-padded
        for (int i = tid; i < 64 * H1N; i += NTHREADS) {
            int c = i / H1N, k = i - c * H1N;
            int o = oc + c;
            sW[k * 65 + c] = (o < H2N) ? W2[o * H1N + k] : 0.f;
        }
        __syncthreads();

        const int o0 = oc + tx;
        const int o1 = oc + tx + 32;
        float bb0 = (o0 < H2N) ? b2[o0] : 0.f;
        float bb1 = (o1 < H2N) ? b2[o1] : 0.f;
        float a00 = bb0, a01 = bb0, a02 = bb0, a03 = bb0;
        float a10 = bb1, a11 = bb1, a12 = bb1, a13 = bb1;

        #pragma unroll 4
        for (int k = 0; k < H1N; k++) {
            float4 a = *reinterpret_cast<const float4*>(&h1T[k * 36 + r0]);
            float w0 = sW[k * 65 + tx];
            float w1 = sW[k * 65 + 32 + tx];
            a00 += a.x * w0; a01 += a.y * w0; a02 += a.z * w0; a03 += a.w * w0;
            a10 += a.x * w1; a11 += a.y * w1; a12 += a.z * w1; a13 += a.w * w1;
        }
        if (o0 < H2N) {
            float v;
            v = a00; h2T[o0 * 36 + r0 + 0] = v > 0.f ? v : SLOPE * v;
            v = a01; h2T[o0 * 36 + r0 + 1] = v > 0.f ? v : SLOPE * v;
            v = a02; h2T[o0 * 36 + r0 + 2] = v > 0.f ? v : SLOPE * v;
            v = a03; h2T[o0 * 36 + r0 + 3] = v > 0.f ? v : SLOPE * v;
        }
        if (o1 < H2N) {
            float v;
            v = a10; h2T[o1 * 36 + r0 + 0] = v > 0.f ? v : SLOPE * v;
            v = a11; h2T[o1 * 36 + r0 + 1] = v > 0.f ? v : SLOPE * v;
            v = a12; h2T[o1 * 36 + r0 + 2] = v > 0.f ? v : SLOPE * v;
            v = a13; h2T[o1 * 36 + r0 + 3] = v > 0.f ? v : SLOPE * v;
        }
        __syncthreads();
    }

    // ---- Layer 3: 600 -> 100, relu.  chunks of 32 out-cols ----
    for (int oc = 0; oc < H3N; oc += 32) {
        for (int i = tid; i < 32 * H2N; i += NTHREADS) {
            int c = i / H2N, k = i - c * H2N;
            int o = oc + c;
            sW[k * 33 + c] = (o < H3N) ? W3[o * H2N + k] : 0.f;
        }
        __syncthreads();

        const int o = oc + tx;
        float bb = (o < H3N) ? b3[o] : 0.f;
        float c0 = bb, c1 = bb, c2 = bb, c3 = bb;
        #pragma unroll 4
        for (int k = 0; k < H2N; k++) {
            float4 a = *reinterpret_cast<const float4*>(&h2T[k * 36 + r0]);
            float w = sW[k * 33 + tx];
            c0 += a.x * w; c1 += a.y * w; c2 += a.z * w; c3 += a.w * w;
        }
        if (o < H3N) {
            h3T[o * 36 + r0 + 0] = fmaxf(c0, 0.f);
            h3T[o * 36 + r0 + 1] = fmaxf(c1, 0.f);
            h3T[o * 36 + r0 + 2] = fmaxf(c2, 0.f);
            h3T[o * 36 + r0 + 3] = fmaxf(c3, 0.f);
        }
        __syncthreads();
    }

    // ---- Layer 4: 100 -> 13, leaky ----
    for (int i = tid; i < 16 * H3N; i += NTHREADS) {
        int o = i & 15, k = i >> 4;
        sW[k * 16 + o] = (o < D_IN) ? W4[o * H3N + k] : 0.f;
    }
    __syncthreads();
    for (int i = tid; i < TILE_M * D_IN; i += NTHREADS) {
        int r = i & (TILE_M - 1), o = i >> 5;
        float acc = b4[o];
        #pragma unroll 4
        for (int k = 0; k < H3N; k++)
            acc += h3T[k * 36 + r] * sW[k * 16 + o];
        t1[r * D_IN + o] = acc > 0.f ? acc : SLOPE * acc;
    }
    __syncthreads();

    // ---- normalize tile rows ----
    if (tid < TILE_M) {
        float s = 0.f;
        #pragma unroll
        for (int o = 0; o < D_IN; o++) { float v = t1[tid * D_IN + o]; s += v * v; }
        rinv[tid] = 1.f / fmaxf(sqrtf(s), EPS_F);
    }
    __syncthreads();
    for (int i = tid; i < TILE_M * D_IN; i += NTHREADS)
        t1[i] *= rinv[i / D_IN];
    __syncthreads();

    // ---- similarity: stage normalized values, max over local rows ----
    float* sv = smem;  // 2048*13 = 26624 floats, reuses dead h2T+sW region
    for (int i = tid; i < B_ROWS * D_IN; i += NTHREADS) sv[i] = g_vn[i];
    __syncthreads();

    #pragma unroll
    for (int pass = 0; pass < 2; pass++) {
        float vb[4][D_IN];
        float mx[4];
        #pragma unroll
        for (int q = 0; q < 4; q++) {
            int b = tid + (pass * 4 + q) * NTHREADS;
            #pragma unroll
            for (int o = 0; o < D_IN; o++) vb[q][o] = sv[b * D_IN + o];
            mx[q] = -3.4e38f;
        }
        for (int r = 0; r < TILE_M; r++) {
            float tr[D_IN];
            #pragma unroll
            for (int o = 0; o < D_IN; o++) tr[o] = t1[r * D_IN + o];
            #pragma unroll
            for (int q = 0; q < 4; q++) {
                float d = 0.f;
                #pragma unroll
                for (int o = 0; o < D_IN; o++) d += vb[q][o] * tr[o];
                mx[q] = fmaxf(mx[q], d);
            }
        }
        #pragma unroll
        for (int q = 0; q < 4; q++) {
            int b = tid + (pass * 4 + q) * NTHREADS;
            atomicMax(&g_umax[b], fkey(SCALE_F * mx[q]));
        }
    }
}

// ---------- kernel 2: decode maxes ----------
__global__ void finish_kernel(float* __restrict__ out) {
    int t = blockIdx.x * blockDim.x + threadIdx.x;
    if (t < B_ROWS) out[t] = funkey(g_umax[t]);
}

extern "C" void kernel_launch(void* const* d_in, const int* in_sizes, int n_in,
                              void* d_out, int out_size)
{
    // identify inputs by element count (all distinct)
    const float *memx = 0, *value = 0, *W1 = 0, *b1 = 0, *W2 = 0, *b2 = 0,
                *W3 = 0, *b3 = 0, *W4 = 0, *b4 = 0;
    for (int i = 0; i < n_in; i++) {
        const float* p = (const float*)d_in[i];
        switch (in_sizes[i]) {
            case M_ROWS * D_IN: memx = p; break;   // 851968
            case B_ROWS * D_IN: value = p; break;  // 26624
            case H1N * D_IN:    W1 = p; break;     // 3900
            case H1N:           b1 = p; break;     // 300
            case H2N * H1N:     W2 = p; break;     // 180000
            case H2N:           b2 = p; break;     // 600
            case H3N * H2N:     W3 = p; break;     // 60000
            case H3N:           b3 = p; break;     // 100
            case D_IN * H3N:    W4 = p; break;     // 1300
            case D_IN:          b4 = p; break;     // 13
            default: break;
        }
    }

    cudaFuncSetAttribute(mlp_sim_kernel,
                         cudaFuncAttributeMaxDynamicSharedMemorySize,
                         SMEM_FLOATS * (int)sizeof(float));

    prep_kernel<<<B_ROWS / NTHREADS, NTHREADS>>>(value);
    mlp_sim_kernel<<<M_ROWS / TILE_M, NTHREADS, SMEM_FLOATS * sizeof(float)>>>(
        memx, W1, b1, W2, b2, W3, b3, W4, b4);
    finish_kernel<<<B_ROWS / NTHREADS, NTHREADS>>>((float*)d_out);
}

// round 5
// speedup vs baseline: 3.0433x; 3.0433x over previous
#include <cuda_runtime.h>
#include <cuda_bf16.h>
#include <math.h>
#include <stdint.h>

#define M_ROWS 65536
#define B_ROWS 2048
#define D_IN   13
#define H1N    300
#define H2N    600
#define H3N    100
#define EPS_F  1e-8f
#define SCALE_F 23.0f
#define SLOPE  0.01f

extern __shared__ char dynsmem[];

// ============ scratch (device globals; no allocations) ============
__device__ uint4 g_A2h[65536ULL * 40];
__device__ uint4 g_A2l[65536ULL * 40];
__device__ uint4 g_A3h[65536ULL * 80];
__device__ uint4 g_A3l[65536ULL * 80];
__device__ uint4 g_W2h[640 * 40];
__device__ uint4 g_W2l[640 * 40];
__device__ uint4 g_W3h[128 * 80];
__device__ uint4 g_W3l[128 * 80];
__device__ float g_h3[65536ULL * 104];
__device__ float g_vn[B_ROWS * D_IN];
__device__ unsigned int g_umax[B_ROWS];

__device__ __forceinline__ unsigned fkey(float f) {
    unsigned b = __float_as_uint(f);
    return (b & 0x80000000u) ? ~b : (b | 0x80000000u);
}
__device__ __forceinline__ float funkey(unsigned u) {
    unsigned b = (u & 0x80000000u) ? (u ^ 0x80000000u) : ~u;
    return __uint_as_float(b);
}
__device__ __forceinline__ uint32_t pk2(float a, float b) {
    __nv_bfloat162 t = __floats2bfloat162_rn(a, b);
    return *reinterpret_cast<uint32_t*>(&t);
}
__device__ __forceinline__ void mma16816(float* d, const uint32_t* a, const uint32_t* b) {
    asm volatile(
        "mma.sync.aligned.m16n8k16.row.col.f32.bf16.bf16.f32 "
        "{%0,%1,%2,%3}, {%4,%5,%6,%7}, {%8,%9}, {%0,%1,%2,%3};"
        : "+f"(d[0]), "+f"(d[1]), "+f"(d[2]), "+f"(d[3])
        : "r"(a[0]), "r"(a[1]), "r"(a[2]), "r"(a[3]), "r"(b[0]), "r"(b[1]));
}

// ---------- normalize value rows, reset maxes ----------
__global__ void prep_kernel(const float* __restrict__ value) {
    int t = blockIdx.x * blockDim.x + threadIdx.x;
    if (t < B_ROWS) {
        float v[D_IN], s = 0.f;
        #pragma unroll
        for (int o = 0; o < D_IN; o++) { v[o] = value[t * D_IN + o]; s += v[o] * v[o]; }
        float inv = 1.f / fmaxf(sqrtf(s), EPS_F);
        #pragma unroll
        for (int o = 0; o < D_IN; o++) g_vn[t * D_IN + o] = v[o] * inv;
        g_umax[t] = 0u;
    }
}

// ---------- weight prep: split into hi/lo padded layouts ----------
__global__ void prep_w2(const float* __restrict__ W2) {
    int e = blockIdx.x * 256 + threadIdx.x;       // [640][40] uint4
    if (e >= 640 * 40) return;
    int n = e / 40, c8 = e % 40;
    union { uint4 v; __nv_bfloat16 b[8]; } hu, lu;
    #pragma unroll
    for (int t = 0; t < 8; t++) {
        int k = c8 * 8 + t;
        float w = (n < H2N && k < H1N) ? W2[n * H1N + k] : 0.f;
        __nv_bfloat16 h = __float2bfloat16(w);
        hu.b[t] = h;
        lu.b[t] = __float2bfloat16(w - __bfloat162float(h));
    }
    g_W2h[e] = hu.v;
    g_W2l[e] = lu.v;
}
__global__ void prep_w3(const float* __restrict__ W3) {
    int e = blockIdx.x * 256 + threadIdx.x;       // [128][80] uint4
    if (e >= 128 * 80) return;
    int n = e / 80, c8 = e % 80;
    union { uint4 v; __nv_bfloat16 b[8]; } hu, lu;
    #pragma unroll
    for (int t = 0; t < 8; t++) {
        int k = c8 * 8 + t;
        float w = (n < H3N && k < H2N) ? W3[n * H2N + k] : 0.f;
        __nv_bfloat16 h = __float2bfloat16(w);
        hu.b[t] = h;
        lu.b[t] = __float2bfloat16(w - __bfloat162float(h));
    }
    g_W3h[e] = hu.v;
    g_W3l[e] = lu.v;
}

// ---------- layer 1: 13 -> 300 relu, write split A2 ----------
#define L1_OUTH 0
#define L1_OUTL 40960
#define L1_SX   81920
#define L1_SW   85248
#define L1_SB   100848
#define L1_SMEM 102048
__global__ void __launch_bounds__(256)
layer1_kernel(const float* __restrict__ memx, const float* __restrict__ W1,
              const float* __restrict__ b1) {
    char* sm = dynsmem;
    uint4* outh = (uint4*)(sm + L1_OUTH);   // [64][40]
    uint4* outl = (uint4*)(sm + L1_OUTL);
    float* sx = (float*)(sm + L1_SX);       // [64][13]
    float* sW = (float*)(sm + L1_SW);       // [300][13]
    float* sb = (float*)(sm + L1_SB);       // [300]
    const int tid = threadIdx.x;
    const int m0 = blockIdx.x * 64;

    for (int i = tid; i < 64 * D_IN; i += 256) sx[i] = memx[(size_t)m0 * D_IN + i];
    for (int i = tid; i < H1N * D_IN; i += 256) sW[i] = W1[i];
    for (int i = tid; i < H1N; i += 256) sb[i] = b1[i];
    __syncthreads();

    for (int i = tid; i < 64 * 40; i += 256) {
        int row = i / 40, c8 = i % 40;
        union { uint4 v; __nv_bfloat16 b[8]; } hu, lu;
        #pragma unroll
        for (int cc = 0; cc < 8; cc++) {
            int c = c8 * 8 + cc;
            float o = 0.f;
            if (c < H1N) {
                o = sb[c];
                #pragma unroll
                for (int k = 0; k < D_IN; k++) o += sx[row * D_IN + k] * sW[c * D_IN + k];
                o = fmaxf(o, 0.f);
            }
            __nv_bfloat16 h = __float2bfloat16(o);
            hu.b[cc] = h;
            lu.b[cc] = __float2bfloat16(o - __bfloat162float(h));
        }
        outh[i] = hu.v;
        outl[i] = lu.v;
    }
    __syncthreads();

    const size_t gbase = (size_t)m0 * 40;
    for (int i = tid; i < 64 * 40; i += 256) {
        g_A2h[gbase + i] = outh[i];
        g_A2l[gbase + i] = outl[i];
    }
}

// ---------- bf16 mma.sync GEMM with 3x hi/lo split ----------
#define SKEW_B 144
#define SA0 0
#define SA1 18432
#define SB0 36864
#define SB1 55296
#define GEMM_SMEM 73728
template<int MODE>
__global__ void __launch_bounds__(256)
gemm_kernel(const float* __restrict__ bias) {
    constexpr int KPU = (MODE == 2) ? 40 : 80;    // uint4 per row of A/W
    constexpr int SEC = (MODE == 2) ? 5 : 10;     // chunks per section
    constexpr int NK  = 3 * SEC;
    char* sm = dynsmem;

    const int tid = threadIdx.x;
    const int wid = tid >> 5, lane = tid & 31;
    const int gid = lane >> 2, tig = lane & 3;
    const int wy = wid >> 2, wx = wid & 3;        // 2 x 4 warp grid
    const int m0 = blockIdx.x * 128;
    const int n0 = blockIdx.y * 128;
    const int srow = tid >> 3, sc8 = tid & 7;     // staging coords

    float acc[4][4][4];
    #pragma unroll
    for (int mi = 0; mi < 4; mi++)
        #pragma unroll
        for (int ni = 0; ni < 4; ni++)
            #pragma unroll
            for (int q = 0; q < 4; q++) acc[mi][ni][q] = 0.f;

    uint4 rA[4], rB[4];
    auto ldg_chunk = [&](int kc) {
        int sec = kc / SEC, idx = kc % SEC;
        const uint4* Asrc = (MODE == 2) ? ((sec < 2) ? g_A2h : g_A2l)
                                        : ((sec < 2) ? g_A3h : g_A3l);
        const uint4* Wsrc = (MODE == 2) ? ((sec == 1) ? g_W2l : g_W2h)
                                        : ((sec == 1) ? g_W3l : g_W3h);
        int k0u = idx * 8;
        #pragma unroll
        for (int j = 0; j < 4; j++)
            rA[j] = Asrc[(size_t)(m0 + srow + 32 * j) * KPU + k0u + sc8];
        #pragma unroll
        for (int j = 0; j < 4; j++)
            rB[j] = Wsrc[(size_t)(n0 + srow + 32 * j) * KPU + k0u + sc8];
    };
    auto sts_chunk = [&](int buf) {
        char* a = sm + (buf ? SA1 : SA0);
        char* b = sm + (buf ? SB1 : SB0);
        #pragma unroll
        for (int j = 0; j < 4; j++)
            *(uint4*)(a + (srow + 32 * j) * SKEW_B + sc8 * 16) = rA[j];
        #pragma unroll
        for (int j = 0; j < 4; j++)
            *(uint4*)(b + (srow + 32 * j) * SKEW_B + sc8 * 16) = rB[j];
    };
    auto compute = [&](int buf) {
        const char* a = sm + (buf ? SA1 : SA0);
        const char* b = sm + (buf ? SB1 : SB0);
        #pragma unroll
        for (int ks = 0; ks < 4; ks++) {
            int kb = ks * 16 + tig * 2;           // even element col
            uint32_t af[4][4], bf[4][2];
            #pragma unroll
            for (int mi = 0; mi < 4; mi++) {
                int r = wy * 64 + mi * 16 + gid;
                af[mi][0] = *(const uint32_t*)(a + r * SKEW_B + kb * 2);
                af[mi][1] = *(const uint32_t*)(a + (r + 8) * SKEW_B + kb * 2);
                af[mi][2] = *(const uint32_t*)(a + r * SKEW_B + (kb + 8) * 2);
                af[mi][3] = *(const uint32_t*)(a + (r + 8) * SKEW_B + (kb + 8) * 2);
            }
            #pragma unroll
            for (int ni = 0; ni < 4; ni++) {
                int n = wx * 32 + ni * 8 + gid;
                bf[ni][0] = *(const uint32_t*)(b + n * SKEW_B + kb * 2);
                bf[ni][1] = *(const uint32_t*)(b + n * SKEW_B + (kb + 8) * 2);
            }
            #pragma unroll
            for (int mi = 0; mi < 4; mi++)
                #pragma unroll
                for (int ni = 0; ni < 4; ni++)
                    mma16816(acc[mi][ni], af[mi], bf[ni]);
        }
    };

    ldg_chunk(0);
    sts_chunk(0);
    __syncthreads();
    for (int kc = 0; kc < NK; kc++) {
        if (kc + 1 < NK) ldg_chunk(kc + 1);
        compute(kc & 1);
        __syncthreads();
        if (kc + 1 < NK) {
            sts_chunk((kc + 1) & 1);
            __syncthreads();
        }
    }

    // ---- epilogue ----
    #pragma unroll
    for (int mi = 0; mi < 4; mi++) {
        #pragma unroll
        for (int ni = 0; ni < 4; ni++) {
            int r0 = m0 + wy * 64 + mi * 16 + gid;
            int c  = n0 + wx * 32 + ni * 8 + tig * 2;
            if (MODE == 2) {
                if (c < H2N) {
                    float bv0 = __ldg(&bias[c]), bv1 = __ldg(&bias[c + 1]);
                    #pragma unroll
                    for (int h = 0; h < 2; h++) {
                        int r = r0 + h * 8;
                        float v0 = acc[mi][ni][h * 2 + 0] + bv0;
                        float v1 = acc[mi][ni][h * 2 + 1] + bv1;
                        v0 = v0 > 0.f ? v0 : SLOPE * v0;
                        v1 = v1 > 0.f ? v1 : SLOPE * v1;
                        float h0 = __bfloat162float(__float2bfloat16(v0));
                        float h1 = __bfloat162float(__float2bfloat16(v1));
                        ((uint32_t*)g_A3h)[(size_t)r * 320 + (c >> 1)] = pk2(h0, h1);
                        ((uint32_t*)g_A3l)[(size_t)r * 320 + (c >> 1)] = pk2(v0 - h0, v1 - h1);
                    }
                }
            } else {
                if (c < 104) {
                    float bv0 = (c < H3N) ? __ldg(&bias[c]) : 0.f;
                    float bv1 = (c + 1 < H3N) ? __ldg(&bias[c + 1]) : 0.f;
                    #pragma unroll
                    for (int h = 0; h < 2; h++) {
                        int r = r0 + h * 8;
                        float v0 = fmaxf(acc[mi][ni][h * 2 + 0] + bv0, 0.f);
                        float v1 = fmaxf(acc[mi][ni][h * 2 + 1] + bv1, 0.f);
                        *(float2*)(&g_h3[(size_t)r * 104 + c]) = make_float2(v0, v1);
                    }
                }
            }
        }
    }
}

// ---------- layer 4 + normalize + similarity max ----------
#define L4_SH3   0
#define L4_T1    3360
#define L4_RINV  3776
#define L4_SV    3808
#define L4_FLOATS (3808 + B_ROWS * D_IN)   // 30432 floats = 121728 B
__global__ void __launch_bounds__(256)
layer4_sim_kernel(const float* __restrict__ W4, const float* __restrict__ b4) {
    float* sm = (float*)dynsmem;
    float* sh3  = sm + L4_SH3;   // [32][105]
    float* t1   = sm + L4_T1;    // [32][13]
    float* rinv = sm + L4_RINV;  // [32]
    float* sv   = sm + L4_SV;    // [2048][13]
    const int tid = threadIdx.x;
    const int m0 = blockIdx.x * 32;

    for (int i = tid; i < 32 * 104; i += 256) {
        int r = i / 104, k = i - r * 104;
        sh3[r * 105 + k] = g_h3[(size_t)(m0 + r) * 104 + k];
    }
    for (int i = tid; i < B_ROWS * D_IN; i += 256) sv[i] = g_vn[i];
    __syncthreads();

    for (int i = tid; i < 32 * D_IN; i += 256) {
        int r = i & 31, o = i >> 5;
        float acc = b4[o];
        #pragma unroll 4
        for (int k = 0; k < H3N; k++) acc += sh3[r * 105 + k] * W4[o * H3N + k];
        t1[r * D_IN + o] = acc > 0.f ? acc : SLOPE * acc;
    }
    __syncthreads();
    if (tid < 32) {
        float s = 0.f;
        #pragma unroll
        for (int o = 0; o < D_IN; o++) { float v = t1[tid * D_IN + o]; s += v * v; }
        rinv[tid] = 1.f / fmaxf(sqrtf(s), EPS_F);
    }
    __syncthreads();
    for (int i = tid; i < 32 * D_IN; i += 256) t1[i] *= rinv[i / D_IN];
    __syncthreads();

    #pragma unroll
    for (int pass = 0; pass < 2; pass++) {
        float vb[4][D_IN];
        float mx[4];
        #pragma unroll
        for (int q = 0; q < 4; q++) {
            int b = tid + (pass * 4 + q) * 256;
            #pragma unroll
            for (int o = 0; o < D_IN; o++) vb[q][o] = sv[b * D_IN + o];
            mx[q] = -3.4e38f;
        }
        for (int r = 0; r < 32; r++) {
            float tr[D_IN];
            #pragma unroll
            for (int o = 0; o < D_IN; o++) tr[o] = t1[r * D_IN + o];
            #pragma unroll
            for (int q = 0; q < 4; q++) {
                float d = 0.f;
                #pragma unroll
                for (int o = 0; o < D_IN; o++) d += vb[q][o] * tr[o];
                mx[q] = fmaxf(mx[q], d);
            }
        }
        #pragma unroll
        for (int q = 0; q < 4; q++) {
            int b = tid + (pass * 4 + q) * 256;
            atomicMax(&g_umax[b], fkey(SCALE_F * mx[q]));
        }
    }
}

__global__ void finish_kernel(float* __restrict__ out) {
    int t = blockIdx.x * blockDim.x + threadIdx.x;
    if (t < B_ROWS) out[t] = funkey(g_umax[t]);
}

// ================= host =================
extern "C" void kernel_launch(void* const* d_in, const int* in_sizes, int n_in,
                              void* d_out, int out_size) {
    const float *memx = 0, *value = 0, *W1 = 0, *b1 = 0, *W2 = 0, *b2 = 0,
                *W3 = 0, *b3 = 0, *W4 = 0, *b4 = 0;
    for (int i = 0; i < n_in; i++) {
        const float* p = (const float*)d_in[i];
        switch (in_sizes[i]) {
            case M_ROWS * D_IN: memx = p; break;
            case B_ROWS * D_IN: value = p; break;
            case H1N * D_IN:    W1 = p; break;
            case H1N:           b1 = p; break;
            case H2N * H1N:     W2 = p; break;
            case H2N:           b2 = p; break;
            case H3N * H2N:     W3 = p; break;
            case H3N:           b3 = p; break;
            case D_IN * H3N:    W4 = p; break;
            case D_IN:          b4 = p; break;
            default: break;
        }
    }

    cudaFuncSetAttribute(layer1_kernel, cudaFuncAttributeMaxDynamicSharedMemorySize, L1_SMEM);
    cudaFuncSetAttribute(gemm_kernel<2>, cudaFuncAttributeMaxDynamicSharedMemorySize, GEMM_SMEM);
    cudaFuncSetAttribute(gemm_kernel<3>, cudaFuncAttributeMaxDynamicSharedMemorySize, GEMM_SMEM);
    cudaFuncSetAttribute(layer4_sim_kernel, cudaFuncAttributeMaxDynamicSharedMemorySize,
                         L4_FLOATS * (int)sizeof(float));

    prep_kernel<<<B_ROWS / 256, 256>>>(value);
    prep_w2<<<(640 * 40 + 255) / 256, 256>>>(W2);
    prep_w3<<<(128 * 80 + 255) / 256, 256>>>(W3);
    layer1_kernel<<<M_ROWS / 64, 256, L1_SMEM>>>(memx, W1, b1);
    gemm_kernel<2><<<dim3(M_ROWS / 128, 5), 256, GEMM_SMEM>>>(b2);
    gemm_kernel<3><<<dim3(M_ROWS / 128, 1), 256, GEMM_SMEM>>>(b3);
    layer4_sim_kernel<<<M_ROWS / 32, 256, L4_FLOATS * sizeof(float)>>>(W4, b4);
    finish_kernel<<<B_ROWS / 256, 256>>>((float*)d_out);
}

// round 6
// speedup vs baseline: 3.1778x; 1.0442x over previous
#include <cuda_runtime.h>
#include <cuda_bf16.h>
#include <math.h>
#include <stdint.h>

#define M_ROWS 65536
#define B_ROWS 2048
#define D_IN   13
#define H1N    300
#define H2N    600
#define H3N    100
#define EPS_F  1e-8f
#define SCALE_F 23.0f
#define SLOPE  0.01f

extern __shared__ char dynsmem[];

// ============ scratch (device globals; no allocations) ============
__device__ uint4 g_A2h[65536ULL * 40];
__device__ uint4 g_A2l[65536ULL * 40];
__device__ uint4 g_A3h[65536ULL * 80];
__device__ uint4 g_A3l[65536ULL * 80];
__device__ uint4 g_W2h[640 * 40];
__device__ uint4 g_W2l[640 * 40];
__device__ uint4 g_W3h[128 * 80];
__device__ uint4 g_W3l[128 * 80];
__device__ float g_h3[65536ULL * 104];
__device__ float g_vn[B_ROWS * D_IN];
__device__ unsigned int g_umax[B_ROWS];

__device__ __forceinline__ unsigned fkey(float f) {
    unsigned b = __float_as_uint(f);
    return (b & 0x80000000u) ? ~b : (b | 0x80000000u);
}
__device__ __forceinline__ float funkey(unsigned u) {
    unsigned b = (u & 0x80000000u) ? (u ^ 0x80000000u) : ~u;
    return __uint_as_float(b);
}
__device__ __forceinline__ uint32_t pk2(float a, float b) {
    __nv_bfloat162 t = __floats2bfloat162_rn(a, b);
    return *reinterpret_cast<uint32_t*>(&t);
}
__device__ __forceinline__ void mma16816(float* d, const uint32_t* a, const uint32_t* b) {
    asm volatile(
        "mma.sync.aligned.m16n8k16.row.col.f32.bf16.bf16.f32 "
        "{%0,%1,%2,%3}, {%4,%5,%6,%7}, {%8,%9}, {%0,%1,%2,%3};"
        : "+f"(d[0]), "+f"(d[1]), "+f"(d[2]), "+f"(d[3])
        : "r"(a[0]), "r"(a[1]), "r"(a[2]), "r"(a[3]), "r"(b[0]), "r"(b[1]));
}

// ---------- normalize value rows, reset maxes ----------
__global__ void prep_kernel(const float* __restrict__ value) {
    int t = blockIdx.x * blockDim.x + threadIdx.x;
    if (t < B_ROWS) {
        float v[D_IN], s = 0.f;
        #pragma unroll
        for (int o = 0; o < D_IN; o++) { v[o] = value[t * D_IN + o]; s += v[o] * v[o]; }
        float inv = 1.f / fmaxf(sqrtf(s), EPS_F);
        #pragma unroll
        for (int o = 0; o < D_IN; o++) g_vn[t * D_IN + o] = v[o] * inv;
        g_umax[t] = 0u;
    }
}

// ---------- weight prep ----------
__global__ void prep_w2(const float* __restrict__ W2) {
    int e = blockIdx.x * 256 + threadIdx.x;       // [640][40] uint4
    if (e >= 640 * 40) return;
    int n = e / 40, c8 = e % 40;
    union { uint4 v; __nv_bfloat16 b[8]; } hu, lu;
    #pragma unroll
    for (int t = 0; t < 8; t++) {
        int k = c8 * 8 + t;
        float w = (n < H2N && k < H1N) ? W2[n * H1N + k] : 0.f;
        __nv_bfloat16 h = __float2bfloat16(w);
        hu.b[t] = h;
        lu.b[t] = __float2bfloat16(w - __bfloat162float(h));
    }
    g_W2h[e] = hu.v;
    g_W2l[e] = lu.v;
}
__global__ void prep_w3(const float* __restrict__ W3) {
    int e = blockIdx.x * 256 + threadIdx.x;       // [128][80] uint4
    if (e >= 128 * 80) return;
    int n = e / 80, c8 = e % 80;
    union { uint4 v; __nv_bfloat16 b[8]; } hu, lu;
    #pragma unroll
    for (int t = 0; t < 8; t++) {
        int k = c8 * 8 + t;
        float w = (n < H3N && k < H2N) ? W3[n * H2N + k] : 0.f;
        __nv_bfloat16 h = __float2bfloat16(w);
        hu.b[t] = h;
        lu.b[t] = __float2bfloat16(w - __bfloat162float(h));
    }
    g_W3h[e] = hu.v;
    g_W3l[e] = lu.v;
}

// ---------- layer 1: 13 -> 300 relu, thread-per-row, broadcast weights ----------
// smem: sW [320][16] f32 (zero-padded), sb [320], sx [256][16]
#define L1_SW   0
#define L1_SB   20480
#define L1_SX   21760
#define L1_SMEM 38144
__global__ void __launch_bounds__(256)
layer1_kernel(const float* __restrict__ memx, const float* __restrict__ W1,
              const float* __restrict__ b1) {
    float* sW = (float*)(dynsmem + L1_SW);   // [320][16]
    float* sb = (float*)(dynsmem + L1_SB);   // [320]
    float* sx = (float*)(dynsmem + L1_SX);   // [256][16]
    const int tid = threadIdx.x;
    const int m0 = blockIdx.x * 256;

    for (int i = tid; i < 320 * 16; i += 256) sW[i] = 0.f;
    for (int i = tid; i < 320; i += 256) sb[i] = (i < H1N) ? b1[i] : 0.f;
    for (int i = tid; i < 256 * 16; i += 256) sx[i] = 0.f;
    __syncthreads();
    for (int i = tid; i < H1N * D_IN; i += 256) sW[(i / D_IN) * 16 + (i % D_IN)] = W1[i];
    for (int i = tid; i < 256 * D_IN; i += 256) sx[(i / D_IN) * 16 + (i % D_IN)] = memx[(size_t)m0 * D_IN + i];
    __syncthreads();

    // per-thread row in registers
    float4 xv[4];
    #pragma unroll
    for (int j = 0; j < 4; j++) xv[j] = *(float4*)(&sx[tid * 16 + 4 * j]);

    const size_t rbase = (size_t)(m0 + tid) * 40;
    #pragma unroll 1
    for (int g = 0; g < 40; g++) {            // 8 cols per group
        union { uint4 v; uint32_t u[4]; } hv, lv;
        #pragma unroll
        for (int p = 0; p < 4; p++) {         // pairs of cols
            float o2[2];
            #pragma unroll
            for (int e = 0; e < 2; e++) {
                int c = g * 8 + p * 2 + e;
                float acc = sb[c];
                #pragma unroll
                for (int j = 0; j < 4; j++) {
                    float4 w = *(float4*)(&sW[c * 16 + 4 * j]);
                    acc += xv[j].x * w.x + xv[j].y * w.y + xv[j].z * w.z + xv[j].w * w.w;
                }
                o2[e] = fmaxf(acc, 0.f);
            }
            float h0 = __bfloat162float(__float2bfloat16(o2[0]));
            float h1 = __bfloat162float(__float2bfloat16(o2[1]));
            hv.u[p] = pk2(h0, h1);
            lv.u[p] = pk2(o2[0] - h0, o2[1] - h1);
        }
        g_A2h[rbase + g] = hv.v;
        g_A2l[rbase + g] = lv.v;
    }
}

// ---------- bf16 mma.sync GEMM with 3x hi/lo split ----------
// MODE 2: 128x128 tile (2x4 warps, 4x4 frags), N total 640
// MODE 3: 128x104 tile (8x1 warps, 1x13 frags), N total 104
#define SKEW_B 144
#define GEMM_SMEM (4 * 128 * SKEW_B)    // 73728; mode3 uses less
template<int MODE>
__global__ void __launch_bounds__(256)
gemm_kernel(const float* __restrict__ bias) {
    constexpr int KPU = (MODE == 2) ? 40 : 80;    // uint4 per row
    constexpr int SEC = (MODE == 2) ? 5 : 10;     // chunks per section
    constexpr int NK  = 3 * SEC;
    constexpr int NB  = (MODE == 2) ? 128 : 104;  // B rows staged
    constexpr int MI  = (MODE == 2) ? 4 : 1;
    constexpr int NI  = (MODE == 2) ? 4 : 13;
    constexpr int ABYTES = 128 * SKEW_B;
    constexpr int BBYTES = NB * SKEW_B;
    char* sm = dynsmem;
    // buffers: A0, A1, B0, B1
    char* sA[2] = { sm, sm + ABYTES };
    char* sB[2] = { sm + 2 * ABYTES, sm + 2 * ABYTES + BBYTES };

    const int tid = threadIdx.x;
    const int wid = tid >> 5, lane = tid & 31;
    const int gid = lane >> 2, tig = lane & 3;
    const int wy = (MODE == 2) ? (wid >> 2) : wid;
    const int wx = (MODE == 2) ? (wid & 3) : 0;
    const int m0 = blockIdx.x * 128;
    const int n0 = blockIdx.y * ((MODE == 2) ? 128 : 104);
    const int srow = tid >> 3, sc8 = tid & 7;

    float acc[MI][NI][4];
    #pragma unroll
    for (int mi = 0; mi < MI; mi++)
        #pragma unroll
        for (int ni = 0; ni < NI; ni++)
            #pragma unroll
            for (int q = 0; q < 4; q++) acc[mi][ni][q] = 0.f;

    constexpr int TOT = 128 + NB;                 // staged rows per chunk
    constexpr int NLD = (TOT * 8 + 255) / 256;    // uint4 per thread
    uint4 rS[NLD];
    auto ldg_chunk = [&](int kc) {
        int sec = kc / SEC, idx = kc % SEC;
        const uint4* Asrc = (MODE == 2) ? ((sec < 2) ? g_A2h : g_A2l)
                                        : ((sec < 2) ? g_A3h : g_A3l);
        const uint4* Wsrc = (MODE == 2) ? ((sec == 1) ? g_W2l : g_W2h)
                                        : ((sec == 1) ? g_W3l : g_W3h);
        int k0u = idx * 8;
        #pragma unroll
        for (int j = 0; j < NLD; j++) {
            int u = tid + j * 256;
            if (u < TOT * 8) {
                int row = u >> 3, uu = u & 7;
                rS[j] = (row < 128)
                    ? Asrc[(size_t)(m0 + row) * KPU + k0u + uu]
                    : Wsrc[(size_t)(n0 + row - 128) * KPU + k0u + uu];
            }
        }
    };
    auto sts_chunk = [&](int buf) {
        #pragma unroll
        for (int j = 0; j < NLD; j++) {
            int u = tid + j * 256;
            if (u < TOT * 8) {
                int row = u >> 3, uu = u & 7;
                char* dst = (row < 128) ? (sA[buf] + row * SKEW_B)
                                        : (sB[buf] + (row - 128) * SKEW_B);
                *(uint4*)(dst + uu * 16) = rS[j];
            }
        }
    };
    auto compute = [&](int buf) {
        const char* a = sA[buf];
        const char* b = sB[buf];
        #pragma unroll
        for (int ks = 0; ks < 4; ks++) {
            int kb = ks * 16 + tig * 2;
            uint32_t af[MI][4], bf[NI][2];
            #pragma unroll
            for (int mi = 0; mi < MI; mi++) {
                int r = (MODE == 2) ? (wy * 64 + mi * 16 + gid) : (wy * 16 + gid);
                af[mi][0] = *(const uint32_t*)(a + r * SKEW_B + kb * 2);
                af[mi][1] = *(const uint32_t*)(a + (r + 8) * SKEW_B + kb * 2);
                af[mi][2] = *(const uint32_t*)(a + r * SKEW_B + (kb + 8) * 2);
                af[mi][3] = *(const uint32_t*)(a + (r + 8) * SKEW_B + (kb + 8) * 2);
            }
            #pragma unroll
            for (int ni = 0; ni < NI; ni++) {
                int n = wx * 32 + ni * 8 + gid;
                bf[ni][0] = *(const uint32_t*)(b + n * SKEW_B + kb * 2);
                bf[ni][1] = *(const uint32_t*)(b + n * SKEW_B + (kb + 8) * 2);
            }
            #pragma unroll
            for (int mi = 0; mi < MI; mi++)
                #pragma unroll
                for (int ni = 0; ni < NI; ni++)
                    mma16816(acc[mi][ni], af[mi], bf[ni]);
        }
    };

    ldg_chunk(0);
    sts_chunk(0);
    __syncthreads();
    for (int kc = 0; kc < NK; kc++) {
        if (kc + 1 < NK) ldg_chunk(kc + 1);
        compute(kc & 1);
        if (kc + 1 < NK) {
            sts_chunk((kc + 1) & 1);   // opposite buffer from the one just read
            __syncthreads();
        }
    }

    // ---- epilogue ----
    #pragma unroll
    for (int mi = 0; mi < MI; mi++) {
        #pragma unroll
        for (int ni = 0; ni < NI; ni++) {
            int r0 = m0 + ((MODE == 2) ? (wy * 64 + mi * 16 + gid) : (wy * 16 + gid));
            int c  = n0 + wx * 32 + ni * 8 + tig * 2;
            if (MODE == 2) {
                if (c < H2N) {
                    float bv0 = __ldg(&bias[c]), bv1 = __ldg(&bias[c + 1]);
                    #pragma unroll
                    for (int h = 0; h < 2; h++) {
                        int r = r0 + h * 8;
                        float v0 = acc[mi][ni][h * 2 + 0] + bv0;
                        float v1 = acc[mi][ni][h * 2 + 1] + bv1;
                        v0 = v0 > 0.f ? v0 : SLOPE * v0;
                        v1 = v1 > 0.f ? v1 : SLOPE * v1;
                        float h0 = __bfloat162float(__float2bfloat16(v0));
                        float h1 = __bfloat162float(__float2bfloat16(v1));
                        ((uint32_t*)g_A3h)[(size_t)r * 320 + (c >> 1)] = pk2(h0, h1);
                        ((uint32_t*)g_A3l)[(size_t)r * 320 + (c >> 1)] = pk2(v0 - h0, v1 - h1);
                    }
                }
            } else {
                float bv0 = (c < H3N) ? __ldg(&bias[c]) : 0.f;
                float bv1 = (c + 1 < H3N) ? __ldg(&bias[c + 1]) : 0.f;
                #pragma unroll
                for (int h = 0; h < 2; h++) {
                    int r = r0 + h * 8;
                    float v0 = fmaxf(acc[mi][ni][h * 2 + 0] + bv0, 0.f);
                    float v1 = fmaxf(acc[mi][ni][h * 2 + 1] + bv1, 0.f);
                    *(float2*)(&g_h3[(size_t)r * 104 + c]) = make_float2(v0, v1);
                }
            }
        }
    }
}

// ---------- layer 4 + normalize + similarity max (64 rows/CTA) ----------
#define L4_SH3   0
#define L4_T1    6720
#define L4_RINV  7552
#define L4_SV    7616
#define L4_FLOATS (7616 + B_ROWS * D_IN)   // 34240 floats = 136960 B
__global__ void __launch_bounds__(256)
layer4_sim_kernel(const float* __restrict__ W4, const float* __restrict__ b4) {
    float* sm = (float*)dynsmem;
    float* sh3  = sm + L4_SH3;   // [64][105]
    float* t1   = sm + L4_T1;    // [64][13]
    float* rinv = sm + L4_RINV;  // [64]
    float* sv   = sm + L4_SV;    // [2048][13]
    const int tid = threadIdx.x;
    const int m0 = blockIdx.x * 64;

    for (int i = tid; i < 64 * 104; i += 256) {
        int r = i / 104, k = i - r * 104;
        sh3[r * 105 + k] = g_h3[(size_t)(m0 + r) * 104 + k];
    }
    for (int i = tid; i < B_ROWS * D_IN; i += 256) sv[i] = g_vn[i];
    __syncthreads();

    for (int i = tid; i < 64 * D_IN; i += 256) {
        int r = i & 63, o = i >> 6;
        float acc = b4[o];
        #pragma unroll 4
        for (int k = 0; k < H3N; k++) acc += sh3[r * 105 + k] * W4[o * H3N + k];
        t1[r * D_IN + o] = acc > 0.f ? acc : SLOPE * acc;
    }
    __syncthreads();
    if (tid < 64) {
        float s = 0.f;
        #pragma unroll
        for (int o = 0; o < D_IN; o++) { float v = t1[tid * D_IN + o]; s += v * v; }
        rinv[tid] = 1.f / fmaxf(sqrtf(s), EPS_F);
    }
    __syncthreads();
    for (int i = tid; i < 64 * D_IN; i += 256) t1[i] *= rinv[i / D_IN];
    __syncthreads();

    #pragma unroll
    for (int pass = 0; pass < 2; pass++) {
        float vb[4][D_IN];
        float mx[4];
        #pragma unroll
        for (int q = 0; q < 4; q++) {
            int b = tid + (pass * 4 + q) * 256;
            #pragma unroll
            for (int o = 0; o < D_IN; o++) vb[q][o] = sv[b * D_IN + o];
            mx[q] = -3.4e38f;
        }
        for (int r = 0; r < 64; r++) {
            float tr[D_IN];
            #pragma unroll
            for (int o = 0; o < D_IN; o++) tr[o] = t1[r * D_IN + o];
            #pragma unroll
            for (int q = 0; q < 4; q++) {
                float d = 0.f;
                #pragma unroll
                for (int o = 0; o < D_IN; o++) d += vb[q][o] * tr[o];
                mx[q] = fmaxf(mx[q], d);
            }
        }
        #pragma unroll
        for (int q = 0; q < 4; q++) {
            int b = tid + (pass * 4 + q) * 256;
            atomicMax(&g_umax[b], fkey(SCALE_F * mx[q]));
        }
    }
}

__global__ void finish_kernel(float* __restrict__ out) {
    int t = blockIdx.x * blockDim.x + threadIdx.x;
    if (t < B_ROWS) out[t] = funkey(g_umax[t]);
}

// ================= host =================
extern "C" void kernel_launch(void* const* d_in, const int* in_sizes, int n_in,
                              void* d_out, int out_size) {
    const float *memx = 0, *value = 0, *W1 = 0, *b1 = 0, *W2 = 0, *b2 = 0,
                *W3 = 0, *b3 = 0, *W4 = 0, *b4 = 0;
    for (int i = 0; i < n_in; i++) {
        const float* p = (const float*)d_in[i];
        switch (in_sizes[i]) {
            case M_ROWS * D_IN: memx = p; break;
            case B_ROWS * D_IN: value = p; break;
            case H1N * D_IN:    W1 = p; break;
            case H1N:           b1 = p; break;
            case H2N * H1N:     W2 = p; break;
            case H2N:           b2 = p; break;
            case H3N * H2N:     W3 = p; break;
            case H3N:           b3 = p; break;
            case D_IN * H3N:    W4 = p; break;
            case D_IN:          b4 = p; break;
            default: break;
        }
    }

    cudaFuncSetAttribute(layer1_kernel, cudaFuncAttributeMaxDynamicSharedMemorySize, L1_SMEM);
    cudaFuncSetAttribute(gemm_kernel<2>, cudaFuncAttributeMaxDynamicSharedMemorySize, GEMM_SMEM);
    cudaFuncSetAttribute(gemm_kernel<3>, cudaFuncAttributeMaxDynamicSharedMemorySize, GEMM_SMEM);
    cudaFuncSetAttribute(layer4_sim_kernel, cudaFuncAttributeMaxDynamicSharedMemorySize,
                         L4_FLOATS * (int)sizeof(float));

    prep_kernel<<<B_ROWS / 256, 256>>>(value);
    prep_w2<<<(640 * 40 + 255) / 256, 256>>>(W2);
    prep_w3<<<(128 * 80 + 255) / 256, 256>>>(W3);
    layer1_kernel<<<M_ROWS / 256, 256, L1_SMEM>>>(memx, W1, b1);
    gemm_kernel<2><<<dim3(M_ROWS / 128, 5), 256, GEMM_SMEM>>>(b2);
    gemm_kernel<3><<<dim3(M_ROWS / 128, 1), 256, GEMM_SMEM>>>(b3);
    layer4_sim_kernel<<<M_ROWS / 64, 256, L4_FLOATS * sizeof(float)>>>(W4, b4);
    finish_kernel<<<B_ROWS / 256, 256>>>((float*)d_out);
}

// round 7
// speedup vs baseline: 3.8445x; 1.2098x over previous
#include <cuda_runtime.h>
#include <cuda_bf16.h>
#include <math.h>
#include <stdint.h>

#define M_ROWS 65536
#define B_ROWS 2048
#define D_IN   13
#define H1N    300
#define H2N    600
#define H3N    100
#define EPS_F  1e-8f
#define SCALE_F 23.0f
#define SLOPE  0.01f

extern __shared__ char dynsmem[];

// ============ scratch (device globals; no allocations) ============
__device__ uint4 g_A2h[65536ULL * 40];
__device__ uint4 g_A2l[65536ULL * 40];
__device__ uint4 g_A3h[65536ULL * 80];
__device__ uint4 g_A3l[65536ULL * 80];
__device__ uint4 g_W2h[640 * 40];
__device__ uint4 g_W2l[640 * 40];
__device__ uint4 g_W3h[128 * 80];
__device__ uint4 g_W3l[128 * 80];
__device__ uint4 g_vns[B_ROWS * 6];     // vn split: [vh|vh|vl], 48 bf16/row
__device__ uint4 g_t1s[65536ULL * 6];   // t1n split: [th|tl|th], 48 bf16/row
__device__ unsigned int g_umax[B_ROWS];

__device__ __forceinline__ unsigned fkey(float f) {
    unsigned b = __float_as_uint(f);
    return (b & 0x80000000u) ? ~b : (b | 0x80000000u);
}
__device__ __forceinline__ float funkey(unsigned u) {
    unsigned b = (u & 0x80000000u) ? (u ^ 0x80000000u) : ~u;
    return __uint_as_float(b);
}
__device__ __forceinline__ uint32_t pk2(float a, float b) {
    __nv_bfloat162 t = __floats2bfloat162_rn(a, b);
    return *reinterpret_cast<uint32_t*>(&t);
}
__device__ __forceinline__ void mma16816(float* d, const uint32_t* a, const uint32_t* b) {
    asm volatile(
        "mma.sync.aligned.m16n8k16.row.col.f32.bf16.bf16.f32 "
        "{%0,%1,%2,%3}, {%4,%5,%6,%7}, {%8,%9}, {%0,%1,%2,%3};"
        : "+f"(d[0]), "+f"(d[1]), "+f"(d[2]), "+f"(d[3])
        : "r"(a[0]), "r"(a[1]), "r"(a[2]), "r"(a[3]), "r"(b[0]), "r"(b[1]));
}

// ---------- weight prep ----------
__global__ void prep_w2(const float* __restrict__ W2) {
    int e = blockIdx.x * 256 + threadIdx.x;       // [640][40] uint4
    if (e >= 640 * 40) return;
    int n = e / 40, c8 = e % 40;
    union { uint4 v; __nv_bfloat16 b[8]; } hu, lu;
    #pragma unroll
    for (int t = 0; t < 8; t++) {
        int k = c8 * 8 + t;
        float w = (n < H2N && k < H1N) ? W2[n * H1N + k] : 0.f;
        __nv_bfloat16 h = __float2bfloat16(w);
        hu.b[t] = h;
        lu.b[t] = __float2bfloat16(w - __bfloat162float(h));
    }
    g_W2h[e] = hu.v;
    g_W2l[e] = lu.v;
}
__global__ void prep_w3(const float* __restrict__ W3) {
    int e = blockIdx.x * 256 + threadIdx.x;       // [128][80] uint4
    if (e >= 128 * 80) return;
    int n = e / 80, c8 = e % 80;
    union { uint4 v; __nv_bfloat16 b[8]; } hu, lu;
    #pragma unroll
    for (int t = 0; t < 8; t++) {
        int k = c8 * 8 + t;
        float w = (n < H3N && k < H2N) ? W3[n * H2N + k] : 0.f;
        __nv_bfloat16 h = __float2bfloat16(w);
        hu.b[t] = h;
        lu.b[t] = __float2bfloat16(w - __bfloat162float(h));
    }
    g_W3h[e] = hu.v;
    g_W3l[e] = lu.v;
}

// ---------- prep vn: normalize value rows, split, reset maxes ----------
__global__ void prep_vn_kernel(const float* __restrict__ value) {
    int t = blockIdx.x * blockDim.x + threadIdx.x;
    if (t >= B_ROWS) return;
    float v[16], s = 0.f;
    #pragma unroll
    for (int o = 0; o < 16; o++) v[o] = 0.f;
    #pragma unroll
    for (int o = 0; o < D_IN; o++) { v[o] = value[t * D_IN + o]; s += v[o] * v[o]; }
    float inv = 1.f / fmaxf(sqrtf(s), EPS_F);
    union { uint4 q[6]; uint32_t u[24]; } out;
    #pragma unroll
    for (int o = 0; o < 16; o += 2) {
        float a = v[o] * inv, b = v[o + 1] * inv;
        float ah = __bfloat162float(__float2bfloat16(a));
        float bh = __bfloat162float(__float2bfloat16(b));
        out.u[o / 2]      = pk2(ah, bh);            // section 0: vh
        out.u[8 + o / 2]  = pk2(ah, bh);            // section 1: vh
        out.u[16 + o / 2] = pk2(a - ah, b - bh);    // section 2: vl
    }
    #pragma unroll
    for (int j = 0; j < 6; j++) g_vns[t * 6 + j] = out.q[j];
    g_umax[t] = 0u;
}

// ---------- layer 1: 13 -> 300 relu, 128 rows/CTA, 2 threads/row ----------
#define L1_SW   0
#define L1_SB   20480
#define L1_SX   21760
#define L1_SMEM 32000
__global__ void __launch_bounds__(256)
layer1_kernel(const float* __restrict__ memx, const float* __restrict__ W1,
              const float* __restrict__ b1) {
    float* sW = (float*)(dynsmem + L1_SW);   // [320][16]
    float* sb = (float*)(dynsmem + L1_SB);   // [320]
    float* sx = (float*)(dynsmem + L1_SX);   // [128][20]
    const int tid = threadIdx.x;
    const int m0 = blockIdx.x * 128;
    const int row = tid & 127, half = tid >> 7;

    for (int i = tid; i < 320 * 16; i += 256) sW[i] = 0.f;
    for (int i = tid; i < 320; i += 256) sb[i] = (i < H1N) ? b1[i] : 0.f;
    for (int i = tid; i < 128 * 20; i += 256) sx[i] = 0.f;
    __syncthreads();
    for (int i = tid; i < H1N * D_IN; i += 256) sW[(i / D_IN) * 16 + (i % D_IN)] = W1[i];
    for (int i = tid; i < 128 * D_IN; i += 256) sx[(i / D_IN) * 20 + (i % D_IN)] = memx[(size_t)m0 * D_IN + i];
    __syncthreads();

    float4 xv[4];
    #pragma unroll
    for (int j = 0; j < 4; j++) xv[j] = *(float4*)(&sx[row * 20 + 4 * j]);

    const size_t rbase = (size_t)(m0 + row) * 40 + half * 20;
    #pragma unroll 1
    for (int gg = 0; gg < 10; gg++) {          // 2 groups (16 cols) per iter
        uint4 hq[2], lq[2];
        #pragma unroll
        for (int g2 = 0; g2 < 2; g2++) {
            union { uint4 v; uint32_t u[4]; } hv, lv;
            #pragma unroll
            for (int p = 0; p < 4; p++) {
                float o2[2];
                #pragma unroll
                for (int e = 0; e < 2; e++) {
                    int c = (half * 20 + gg * 2 + g2) * 8 + p * 2 + e;
                    float acc = sb[c];
                    #pragma unroll
                    for (int j = 0; j < 4; j++) {
                        float4 w = *(float4*)(&sW[c * 16 + 4 * j]);
                        acc += xv[j].x * w.x + xv[j].y * w.y + xv[j].z * w.z + xv[j].w * w.w;
                    }
                    o2[e] = fmaxf(acc, 0.f);
                }
                float h0 = __bfloat162float(__float2bfloat16(o2[0]));
                float h1 = __bfloat162float(__float2bfloat16(o2[1]));
                hv.u[p] = pk2(h0, h1);
                lv.u[p] = pk2(o2[0] - h0, o2[1] - h1);
            }
            hq[g2] = hv.v; lq[g2] = lv.v;
        }
        g_A2h[rbase + gg * 2] = hq[0];
        g_A2h[rbase + gg * 2 + 1] = hq[1];
        g_A2l[rbase + gg * 2] = lq[0];
        g_A2l[rbase + gg * 2 + 1] = lq[1];
    }
}

// ---------- bf16 mma.sync GEMM with 3x hi/lo split ----------
// MODE 2: 128x128 tile (2x4 warps, 4x4 frags), writes split A3
// MODE 3: 128x104 tile (8x1 warps, 1x13 frags), fused layer4+normalize+t1-split
#define SKEW_B 144
#define GEMM2_SMEM (4 * 128 * SKEW_B)                 // 73728
#define G3_BUF_END (2 * 128 * SKEW_B + 2 * 104 * SKEW_B)  // 66816
#define G3_W4   G3_BUF_END
#define G3_B4   (G3_W4 + 5200)
#define G3_SMEM (G3_B4 + 64)                          // 72080
template<int MODE>
__global__ void __launch_bounds__(256)
gemm_kernel(const float* __restrict__ bias,
            const float* __restrict__ W4, const float* __restrict__ b4) {
    constexpr int KPU = (MODE == 2) ? 40 : 80;
    constexpr int SEC = (MODE == 2) ? 5 : 10;
    constexpr int NK  = 3 * SEC;
    constexpr int NB  = (MODE == 2) ? 128 : 104;
    constexpr int MI  = (MODE == 2) ? 4 : 1;
    constexpr int NI  = (MODE == 2) ? 4 : 13;
    constexpr int ABYTES = 128 * SKEW_B;
    constexpr int BBYTES = NB * SKEW_B;
    char* sm = dynsmem;
    char* sA[2] = { sm, sm + ABYTES };
    char* sB[2] = { sm + 2 * ABYTES, sm + 2 * ABYTES + BBYTES };

    const int tid = threadIdx.x;
    const int wid = tid >> 5, lane = tid & 31;
    const int gid = lane >> 2, tig = lane & 3;
    const int wy = (MODE == 2) ? (wid >> 2) : wid;
    const int wx = (MODE == 2) ? (wid & 3) : 0;
    const int m0 = blockIdx.x * 128;
    const int n0 = blockIdx.y * ((MODE == 2) ? 128 : 104);

    if (MODE == 3) {   // stage W4/b4 for fused tail
        float* sW4 = (float*)(sm + G3_W4);
        float* sb4 = (float*)(sm + G3_B4);
        for (int i = tid; i < D_IN * H3N; i += 256) sW4[i] = W4[i];
        if (tid < D_IN) sb4[tid] = b4[tid];
    }

    float acc[MI][NI][4];
    #pragma unroll
    for (int mi = 0; mi < MI; mi++)
        #pragma unroll
        for (int ni = 0; ni < NI; ni++)
            #pragma unroll
            for (int q = 0; q < 4; q++) acc[mi][ni][q] = 0.f;

    constexpr int TOT = 128 + NB;
    constexpr int NLD = (TOT * 8 + 255) / 256;
    uint4 rS[NLD];
    auto ldg_chunk = [&](int kc) {
        int sec = kc / SEC, idx = kc % SEC;
        const uint4* Asrc = (MODE == 2) ? ((sec < 2) ? g_A2h : g_A2l)
                                        : ((sec < 2) ? g_A3h : g_A3l);
        const uint4* Wsrc = (MODE == 2) ? ((sec == 1) ? g_W2l : g_W2h)
                                        : ((sec == 1) ? g_W3l : g_W3h);
        int k0u = idx * 8;
        #pragma unroll
        for (int j = 0; j < NLD; j++) {
            int u = tid + j * 256;
            if (u < TOT * 8) {
                int row = u >> 3, uu = u & 7;
                rS[j] = (row < 128)
                    ? Asrc[(size_t)(m0 + row) * KPU + k0u + uu]
                    : Wsrc[(size_t)(n0 + row - 128) * KPU + k0u + uu];
            }
        }
    };
    auto sts_chunk = [&](int buf) {
        #pragma unroll
        for (int j = 0; j < NLD; j++) {
            int u = tid + j * 256;
            if (u < TOT * 8) {
                int row = u >> 3, uu = u & 7;
                char* dst = (row < 128) ? (sA[buf] + row * SKEW_B)
                                        : (sB[buf] + (row - 128) * SKEW_B);
                *(uint4*)(dst + uu * 16) = rS[j];
            }
        }
    };
    auto compute = [&](int buf) {
        const char* a = sA[buf];
        const char* b = sB[buf];
        #pragma unroll
        for (int ks = 0; ks < 4; ks++) {
            int kb = ks * 16 + tig * 2;
            uint32_t af[MI][4], bf[NI][2];
            #pragma unroll
            for (int mi = 0; mi < MI; mi++) {
                int r = (MODE == 2) ? (wy * 64 + mi * 16 + gid) : (wy * 16 + gid);
                af[mi][0] = *(const uint32_t*)(a + r * SKEW_B + kb * 2);
                af[mi][1] = *(const uint32_t*)(a + (r + 8) * SKEW_B + kb * 2);
                af[mi][2] = *(const uint32_t*)(a + r * SKEW_B + (kb + 8) * 2);
                af[mi][3] = *(const uint32_t*)(a + (r + 8) * SKEW_B + (kb + 8) * 2);
            }
            #pragma unroll
            for (int ni = 0; ni < NI; ni++) {
                int n = wx * 32 + ni * 8 + gid;
                bf[ni][0] = *(const uint32_t*)(b + n * SKEW_B + kb * 2);
                bf[ni][1] = *(const uint32_t*)(b + n * SKEW_B + (kb + 8) * 2);
            }
            #pragma unroll
            for (int mi = 0; mi < MI; mi++)
                #pragma unroll
                for (int ni = 0; ni < NI; ni++)
                    mma16816(acc[mi][ni], af[mi], bf[ni]);
        }
    };

    ldg_chunk(0);
    sts_chunk(0);
    __syncthreads();
    for (int kc = 0; kc < NK; kc++) {
        if (kc + 1 < NK) ldg_chunk(kc + 1);
        compute(kc & 1);
        if (kc + 1 < NK) {
            sts_chunk((kc + 1) & 1);
            __syncthreads();
        }
    }

    if (MODE == 2) {
        #pragma unroll
        for (int mi = 0; mi < MI; mi++) {
            #pragma unroll
            for (int ni = 0; ni < NI; ni++) {
                int r0 = m0 + wy * 64 + mi * 16 + gid;
                int c  = n0 + wx * 32 + ni * 8 + tig * 2;
                if (c < H2N) {
                    float bv0 = __ldg(&bias[c]), bv1 = __ldg(&bias[c + 1]);
                    #pragma unroll
                    for (int h = 0; h < 2; h++) {
                        int r = r0 + h * 8;
                        float v0 = acc[mi][ni][h * 2 + 0] + bv0;
                        float v1 = acc[mi][ni][h * 2 + 1] + bv1;
                        v0 = v0 > 0.f ? v0 : SLOPE * v0;
                        v1 = v1 > 0.f ? v1 : SLOPE * v1;
                        float h0 = __bfloat162float(__float2bfloat16(v0));
                        float h1 = __bfloat162float(__float2bfloat16(v1));
                        ((uint32_t*)g_A3h)[(size_t)r * 320 + (c >> 1)] = pk2(h0, h1);
                        ((uint32_t*)g_A3l)[(size_t)r * 320 + (c >> 1)] = pk2(v0 - h0, v1 - h1);
                    }
                }
            }
        }
    } else {
        // ---- fused tail: h3 -> smem, layer4 + normalize + t1 split ----
        __syncthreads();                     // buffers dead; reuse as h3s
        float* h3s = (float*)sm;             // [128][106]
        #pragma unroll
        for (int ni = 0; ni < NI; ni++) {
            int c = ni * 8 + tig * 2;
            float bv0 = (c < H3N) ? __ldg(&bias[c]) : 0.f;
            float bv1 = (c + 1 < H3N) ? __ldg(&bias[c + 1]) : 0.f;
            #pragma unroll
            for (int h = 0; h < 2; h++) {
                int r = wy * 16 + gid + h * 8;
                float v0 = fmaxf(acc[0][ni][h * 2 + 0] + bv0, 0.f);
                float v1 = fmaxf(acc[0][ni][h * 2 + 1] + bv1, 0.f);
                *(float2*)(&h3s[r * 106 + c]) = make_float2(v0, v1);
            }
        }
        __syncthreads();
        if (tid < 128) {
            const float* sW4 = (const float*)(sm + G3_W4);
            const float* sb4 = (const float*)(sm + G3_B4);
            int r = tid;
            float o[D_IN];
            #pragma unroll
            for (int oo = 0; oo < D_IN; oo++) o[oo] = sb4[oo];
            #pragma unroll 4
            for (int k = 0; k < H3N; k++) {
                float hv = h3s[r * 106 + k];
                #pragma unroll
                for (int oo = 0; oo < D_IN; oo++) o[oo] += hv * sW4[oo * H3N + k];
            }
            float s = 0.f;
            #pragma unroll
            for (int oo = 0; oo < D_IN; oo++) {
                o[oo] = o[oo] > 0.f ? o[oo] : SLOPE * o[oo];
                s += o[oo] * o[oo];
            }
            float inv = 1.f / fmaxf(sqrtf(s), EPS_F);
            float t[16];
            #pragma unroll
            for (int oo = 0; oo < 16; oo++) t[oo] = (oo < D_IN) ? o[oo] * inv : 0.f;
            union { uint4 q[6]; uint32_t u[24]; } out;
            #pragma unroll
            for (int oo = 0; oo < 16; oo += 2) {
                float ah = __bfloat162float(__float2bfloat16(t[oo]));
                float bh = __bfloat162float(__float2bfloat16(t[oo + 1]));
                out.u[oo / 2]      = pk2(ah, bh);                        // th
                out.u[8 + oo / 2]  = pk2(t[oo] - ah, t[oo + 1] - bh);    // tl
                out.u[16 + oo / 2] = pk2(ah, bh);                        // th
            }
            #pragma unroll
            for (int j = 0; j < 6; j++) g_t1s[(size_t)(m0 + r) * 6 + j] = out.q[j];
        }
    }
}

// ---------- similarity via split-bf16 mma: max over t1 rows ----------
// CTA: 128 t1-rows (N), loops 8 vn-chunks of 256 (M). K=48 (3 sections).
#define SIM_SV  0
#define SIM_ST  196608
#define SIM_SMEM 208896
__global__ void __launch_bounds__(256, 1)
sim_kernel() {
    char* sm = dynsmem;
    char* sv  = sm + SIM_SV;    // [2048][96B]
    char* st1 = sm + SIM_ST;    // [128][96B]
    const int tid = threadIdx.x;
    const int wid = tid >> 5, lane = tid & 31;
    const int gid = lane >> 2, tig = lane & 3;
    const int wy = wid >> 2, wx = wid & 3;   // 2(M) x 4(N) warps
    const int n0 = blockIdx.x * 128;

    for (int i = tid; i < B_ROWS * 6; i += 256) ((uint4*)sv)[i] = g_vns[i];
    for (int i = tid; i < 128 * 6; i += 256)   ((uint4*)st1)[i] = g_t1s[(size_t)n0 * 6 + i];
    __syncthreads();

    // B fragments (t1) are chunk-invariant: preload
    uint32_t bf[3][4][2];
    #pragma unroll
    for (int s = 0; s < 3; s++)
        #pragma unroll
        for (int ni = 0; ni < 4; ni++) {
            int n = wx * 32 + ni * 8 + gid;
            bf[s][ni][0] = *(const uint32_t*)(st1 + n * 96 + s * 32 + tig * 4);
            bf[s][ni][1] = *(const uint32_t*)(st1 + n * 96 + s * 32 + 16 + tig * 4);
        }

    for (int c = 0; c < 8; c++) {
        float acc[8][4][4];
        #pragma unroll
        for (int mi = 0; mi < 8; mi++)
            #pragma unroll
            for (int ni = 0; ni < 4; ni++)
                #pragma unroll
                for (int q = 0; q < 4; q++) acc[mi][ni][q] = 0.f;

        const char* va = sv + (c * 256 + wy * 128) * 96;
        #pragma unroll
        for (int s = 0; s < 3; s++) {
            #pragma unroll
            for (int mi = 0; mi < 8; mi++) {
                int r = mi * 16 + gid;
                uint32_t af[4];
                af[0] = *(const uint32_t*)(va + r * 96 + s * 32 + tig * 4);
                af[1] = *(const uint32_t*)(va + (r + 8) * 96 + s * 32 + tig * 4);
                af[2] = *(const uint32_t*)(va + r * 96 + s * 32 + 16 + tig * 4);
                af[3] = *(const uint32_t*)(va + (r + 8) * 96 + s * 32 + 16 + tig * 4);
                #pragma unroll
                for (int ni = 0; ni < 4; ni++)
                    mma16816(acc[mi][ni], af, bf[s][ni]);
            }
        }
        // max over this CTA's 128 t1-cols, then atomicMax per vn row
        #pragma unroll
        for (int mi = 0; mi < 8; mi++) {
            #pragma unroll
            for (int h = 0; h < 2; h++) {
                float mx = -3.4e38f;
                #pragma unroll
                for (int ni = 0; ni < 4; ni++)
                    mx = fmaxf(mx, fmaxf(acc[mi][ni][h * 2], acc[mi][ni][h * 2 + 1]));
                mx = fmaxf(mx, __shfl_xor_sync(0xFFFFFFFF, mx, 1));
                mx = fmaxf(mx, __shfl_xor_sync(0xFFFFFFFF, mx, 2));
                if (tig == 0) {
                    int row = c * 256 + wy * 128 + mi * 16 + gid + 8 * h;
                    atomicMax(&g_umax[row], fkey(SCALE_F * mx));
                }
            }
        }
    }
}

__global__ void finish_kernel(float* __restrict__ out) {
    int t = blockIdx.x * blockDim.x + threadIdx.x;
    if (t < B_ROWS) out[t] = funkey(g_umax[t]);
}

// ================= host =================
extern "C" void kernel_launch(void* const* d_in, const int* in_sizes, int n_in,
                              void* d_out, int out_size) {
    const float *memx = 0, *value = 0, *W1 = 0, *b1 = 0, *W2 = 0, *b2 = 0,
                *W3 = 0, *b3 = 0, *W4 = 0, *b4 = 0;
    for (int i = 0; i < n_in; i++) {
        const float* p = (const float*)d_in[i];
        switch (in_sizes[i]) {
            case M_ROWS * D_IN: memx = p; break;
            case B_ROWS * D_IN: value = p; break;
            case H1N * D_IN:    W1 = p; break;
            case H1N:           b1 = p; break;
            case H2N * H1N:     W2 = p; break;
            case H2N:           b2 = p; break;
            case H3N * H2N:     W3 = p; break;
            case H3N:           b3 = p; break;
            case D_IN * H3N:    W4 = p; break;
            case D_IN:          b4 = p; break;
            default: break;
        }
    }

    cudaFuncSetAttribute(layer1_kernel, cudaFuncAttributeMaxDynamicSharedMemorySize, L1_SMEM);
    cudaFuncSetAttribute(gemm_kernel<2>, cudaFuncAttributeMaxDynamicSharedMemorySize, GEMM2_SMEM);
    cudaFuncSetAttribute(gemm_kernel<3>, cudaFuncAttributeMaxDynamicSharedMemorySize, G3_SMEM);
    cudaFuncSetAttribute(sim_kernel, cudaFuncAttributeMaxDynamicSharedMemorySize, SIM_SMEM);

    prep_w2<<<(640 * 40 + 255) / 256, 256>>>(W2);
    prep_w3<<<(128 * 80 + 255) / 256, 256>>>(W3);
    layer1_kernel<<<M_ROWS / 128, 256, L1_SMEM>>>(memx, W1, b1);
    gemm_kernel<2><<<dim3(M_ROWS / 128, 5), 256, GEMM2_SMEM>>>(b2, 0, 0);
    prep_vn_kernel<<<B_ROWS / 256, 256>>>(value);
    gemm_kernel<3><<<dim3(M_ROWS / 128, 1), 256, G3_SMEM>>>(b3, W4, b4);
    sim_kernel<<<M_ROWS / 128, 256, SIM_SMEM>>>();
    finish_kernel<<<B_ROWS / 256, 256>>>((float*)d_out);
}

// round 9
// speedup vs baseline: 4.5793x; 1.1911x over previous
#include <cuda_runtime.h>
#include <cuda_bf16.h>
#include <math.h>
#include <stdint.h>

#define M_ROWS 65536
#define B_ROWS 2048
#define D_IN   13
#define H1N    300
#define H2N    600
#define H3N    100
#define EPS_F  1e-8f
#define SCALE_F 23.0f
#define SLOPE  0.01f

extern __shared__ char dynsmem[];

// ============ scratch (device globals; no allocations) ============
__device__ uint4 g_A2h[65536ULL * 40];
__device__ uint4 g_A2l[65536ULL * 40];
__device__ uint4 g_A3h[65536ULL * 80];
__device__ uint4 g_A3l[65536ULL * 80];
__device__ uint4 g_W2h[640 * 40];
__device__ uint4 g_W2l[640 * 40];
__device__ uint4 g_W3h[128 * 80];
__device__ uint4 g_W3l[128 * 80];
__device__ uint4 g_vns[B_ROWS * 6];     // vn split: [vh|vh|vl], 48 bf16/row
__device__ uint4 g_t1s[65536ULL * 6];   // t1n split: [th|tl|th], 48 bf16/row
__device__ unsigned int g_umax[B_ROWS];

__device__ __forceinline__ unsigned fkey(float f) {
    unsigned b = __float_as_uint(f);
    return (b & 0x80000000u) ? ~b : (b | 0x80000000u);
}
__device__ __forceinline__ float funkey(unsigned u) {
    unsigned b = (u & 0x80000000u) ? (u ^ 0x80000000u) : ~u;
    return __uint_as_float(b);
}
__device__ __forceinline__ uint32_t pk2(float a, float b) {
    __nv_bfloat162 t = __floats2bfloat162_rn(a, b);
    return *reinterpret_cast<uint32_t*>(&t);
}
__device__ __forceinline__ uint32_t smem_u32(const void* p) {
    uint32_t a;
    asm("{ .reg .u64 t; cvta.to.shared.u64 t, %1; cvt.u32.u64 %0, t; }" : "=r"(a) : "l"(p));
    return a;
}
__device__ __forceinline__ void mma16816(float* d, const uint32_t* a, const uint32_t* b) {
    asm volatile(
        "mma.sync.aligned.m16n8k16.row.col.f32.bf16.bf16.f32 "
        "{%0,%1,%2,%3}, {%4,%5,%6,%7}, {%8,%9}, {%0,%1,%2,%3};"
        : "+f"(d[0]), "+f"(d[1]), "+f"(d[2]), "+f"(d[3])
        : "r"(a[0]), "r"(a[1]), "r"(a[2]), "r"(a[3]), "r"(b[0]), "r"(b[1]));
}
__device__ __forceinline__ void ldm_x4(uint32_t* r, uint32_t addr) {
    asm volatile("ldmatrix.sync.aligned.m8n8.x4.shared.b16 {%0,%1,%2,%3}, [%4];"
        : "=r"(r[0]), "=r"(r[1]), "=r"(r[2]), "=r"(r[3]) : "r"(addr));
}
__device__ __forceinline__ void ldm_x2(uint32_t* r, uint32_t addr) {
    asm volatile("ldmatrix.sync.aligned.m8n8.x2.shared.b16 {%0,%1}, [%2];"
        : "=r"(r[0]), "=r"(r[1]) : "r"(addr));
}
__device__ __forceinline__ void cpa16(uint32_t dst, const void* src) {
    asm volatile("cp.async.cg.shared.global [%0], [%1], 16;" :: "r"(dst), "l"(src));
}
#define CP_COMMIT() asm volatile("cp.async.commit_group;" ::: "memory")
#define CP_WAIT(n)  asm volatile("cp.async.wait_group %0;" :: "n"(n) : "memory")

// ---------- weight prep ----------
__global__ void prep_w2(const float* __restrict__ W2) {
    int e = blockIdx.x * 256 + threadIdx.x;       // [640][40] uint4
    if (e >= 640 * 40) return;
    int n = e / 40, c8 = e % 40;
    union { uint4 v; __nv_bfloat16 b[8]; } hu, lu;
    #pragma unroll
    for (int t = 0; t < 8; t++) {
        int k = c8 * 8 + t;
        float w = (n < H2N && k < H1N) ? W2[n * H1N + k] : 0.f;
        __nv_bfloat16 h = __float2bfloat16(w);
        hu.b[t] = h;
        lu.b[t] = __float2bfloat16(w - __bfloat162float(h));
    }
    g_W2h[e] = hu.v;
    g_W2l[e] = lu.v;
}
__global__ void prep_w3(const float* __restrict__ W3) {
    int e = blockIdx.x * 256 + threadIdx.x;       // [128][80] uint4
    if (e >= 128 * 80) return;
    int n = e / 80, c8 = e % 80;
    union { uint4 v; __nv_bfloat16 b[8]; } hu, lu;
    #pragma unroll
    for (int t = 0; t < 8; t++) {
        int k = c8 * 8 + t;
        float w = (n < H3N && k < H2N) ? W3[n * H2N + k] : 0.f;
        __nv_bfloat16 h = __float2bfloat16(w);
        hu.b[t] = h;
        lu.b[t] = __float2bfloat16(w - __bfloat162float(h));
    }
    g_W3h[e] = hu.v;
    g_W3l[e] = lu.v;
}

// ---------- prep vn ----------
__global__ void prep_vn_kernel(const float* __restrict__ value) {
    int t = blockIdx.x * blockDim.x + threadIdx.x;
    if (t >= B_ROWS) return;
    float v[16], s = 0.f;
    #pragma unroll
    for (int o = 0; o < 16; o++) v[o] = 0.f;
    #pragma unroll
    for (int o = 0; o < D_IN; o++) { v[o] = value[t * D_IN + o]; s += v[o] * v[o]; }
    float inv = 1.f / fmaxf(sqrtf(s), EPS_F);
    union { uint4 q[6]; uint32_t u[24]; } out;
    #pragma unroll
    for (int o = 0; o < 16; o += 2) {
        float a = v[o] * inv, b = v[o + 1] * inv;
        float ah = __bfloat162float(__float2bfloat16(a));
        float bh = __bfloat162float(__float2bfloat16(b));
        out.u[o / 2]      = pk2(ah, bh);
        out.u[8 + o / 2]  = pk2(ah, bh);
        out.u[16 + o / 2] = pk2(a - ah, b - bh);
    }
    #pragma unroll
    for (int j = 0; j < 6; j++) g_vns[t * 6 + j] = out.q[j];
    g_umax[t] = 0u;
}

// ---------- layer 1 ----------
#define L1_SW   0
#define L1_SB   20480
#define L1_SX   21760
#define L1_SMEM 32000
__global__ void __launch_bounds__(256)
layer1_kernel(const float* __restrict__ memx, const float* __restrict__ W1,
              const float* __restrict__ b1) {
    float* sW = (float*)(dynsmem + L1_SW);   // [320][16]
    float* sb = (float*)(dynsmem + L1_SB);   // [320]
    float* sx = (float*)(dynsmem + L1_SX);   // [128][20]
    const int tid = threadIdx.x;
    const int m0 = blockIdx.x * 128;
    const int row = tid & 127, half = tid >> 7;

    for (int i = tid; i < 320 * 16; i += 256) sW[i] = 0.f;
    for (int i = tid; i < 320; i += 256) sb[i] = (i < H1N) ? b1[i] : 0.f;
    for (int i = tid; i < 128 * 20; i += 256) sx[i] = 0.f;
    __syncthreads();
    for (int i = tid; i < H1N * D_IN; i += 256) sW[(i / D_IN) * 16 + (i % D_IN)] = W1[i];
    for (int i = tid; i < 128 * D_IN; i += 256) sx[(i / D_IN) * 20 + (i % D_IN)] = memx[(size_t)m0 * D_IN + i];
    __syncthreads();

    float4 xv[4];
    #pragma unroll
    for (int j = 0; j < 4; j++) xv[j] = *(float4*)(&sx[row * 20 + 4 * j]);

    const size_t rbase = (size_t)(m0 + row) * 40 + half * 20;
    #pragma unroll 1
    for (int gg = 0; gg < 10; gg++) {
        uint4 hq[2], lq[2];
        #pragma unroll
        for (int g2 = 0; g2 < 2; g2++) {
            union { uint4 v; uint32_t u[4]; } hv, lv;
            #pragma unroll
            for (int p = 0; p < 4; p++) {
                float o2[2];
                #pragma unroll
                for (int e = 0; e < 2; e++) {
                    int c = (half * 20 + gg * 2 + g2) * 8 + p * 2 + e;
                    float acc = sb[c];
                    #pragma unroll
                    for (int j = 0; j < 4; j++) {
                        float4 w = *(float4*)(&sW[c * 16 + 4 * j]);
                        acc += xv[j].x * w.x + xv[j].y * w.y + xv[j].z * w.z + xv[j].w * w.w;
                    }
                    o2[e] = fmaxf(acc, 0.f);
                }
                float h0 = __bfloat162float(__float2bfloat16(o2[0]));
                float h1 = __bfloat162float(__float2bfloat16(o2[1]));
                hv.u[p] = pk2(h0, h1);
                lv.u[p] = pk2(o2[0] - h0, o2[1] - h1);
            }
            hq[g2] = hv.v; lq[g2] = lv.v;
        }
        g_A2h[rbase + gg * 2] = hq[0];
        g_A2h[rbase + gg * 2 + 1] = hq[1];
        g_A2l[rbase + gg * 2] = lq[0];
        g_A2l[rbase + gg * 2 + 1] = lq[1];
    }
}

// ---------- bf16 mma GEMM: cp.async 3-stage + ldmatrix ----------
#define SKEW_B 144
#define STAGES 3
// MODE2: stage = (128 A + 128 B) rows * 144B = 36864; MODE3: (128+104)*144 = 33408
#define G2_STAGE (256 * SKEW_B)
#define G3_STAGE (232 * SKEW_B)
#define GEMM2_SMEM (STAGES * G2_STAGE)                // 110592
#define G3_W4   (STAGES * G3_STAGE)
#define G3_B4   (G3_W4 + 5200)
#define G3_SMEM (G3_B4 + 64)                          // 105488
template<int MODE>
__global__ void __launch_bounds__(256)
gemm_kernel(const float* __restrict__ bias,
            const float* __restrict__ W4, const float* __restrict__ b4) {
    constexpr int KPU = (MODE == 2) ? 40 : 80;
    constexpr int SEC = (MODE == 2) ? 5 : 10;
    constexpr int NK  = 3 * SEC;
    constexpr int NB  = (MODE == 2) ? 128 : 104;
    constexpr int MI  = (MODE == 2) ? 4 : 1;
    constexpr int NI  = (MODE == 2) ? 4 : 13;
    constexpr int STAGE = (MODE == 2) ? G2_STAGE : G3_STAGE;
    constexpr int BOFF = 128 * SKEW_B;                // B region within stage
    char* sm = dynsmem;
    const uint32_t smb = smem_u32(sm);

    const int tid = threadIdx.x;
    const int wid = tid >> 5, lane = tid & 31;
    const int gid = lane >> 2, tig = lane & 3;
    const int wy = (MODE == 2) ? (wid >> 2) : wid;
    const int wx = (MODE == 2) ? (wid & 3) : 0;
    const int m0 = blockIdx.x * 128;
    const int n0 = blockIdx.y * ((MODE == 2) ? 128 : 104);

    if (MODE == 3) {
        float* sW4 = (float*)(sm + G3_W4);
        float* sb4 = (float*)(sm + G3_B4);
        for (int i = tid; i < D_IN * H3N; i += 256) sW4[i] = W4[i];
        if (tid < D_IN) sb4[tid] = b4[tid];
    }

    float acc[MI][NI][4];
    #pragma unroll
    for (int mi = 0; mi < MI; mi++)
        #pragma unroll
        for (int ni = 0; ni < NI; ni++)
            #pragma unroll
            for (int q = 0; q < 4; q++) acc[mi][ni][q] = 0.f;

    // ldmatrix lane offsets (within a stage)
    const int lrow = lane & 15, lkh = lane >> 4;      // row-in-16, k-half
    uint32_t aoff[MI], boff[(NI + 1) / 2];
    #pragma unroll
    for (int mi = 0; mi < MI; mi++) {
        int r = ((MODE == 2) ? (wy * 64 + mi * 16) : (wy * 16)) + lrow;
        aoff[mi] = smb + r * SKEW_B + lkh * 16;
    }
    #pragma unroll
    for (int p = 0; p < (NI + 1) / 2; p++) {
        int nb = wx * 32 + p * 16;
        if (2 * p + 1 < NI || MODE == 2) {
            boff[p] = smb + BOFF + (nb + lrow) * SKEW_B + lkh * 16;
        } else {  // tail x2 (MODE 3, ni=12): lanes 0-15, n rows 96-103
            int l16 = lane & 15;
            boff[p] = smb + BOFF + (96 + (l16 & 7)) * SKEW_B + (l16 >> 3) * 16;
        }
    }

    constexpr int TOT8 = (128 + NB) * 8;
    constexpr int NLD = (TOT8 + 255) / 256;
    auto issue_copy = [&](int kc, int st) {
        int sec = kc / SEC, idx = kc % SEC;
        const uint4* Asrc = (MODE == 2) ? ((sec < 2) ? g_A2h : g_A2l)
                                        : ((sec < 2) ? g_A3h : g_A3l);
        const uint4* Wsrc = (MODE == 2) ? ((sec == 1) ? g_W2l : g_W2h)
                                        : ((sec == 1) ? g_W3l : g_W3h);
        int k0u = idx * 8;
        uint32_t sb0 = smb + st * STAGE;
        #pragma unroll
        for (int j = 0; j < NLD; j++) {
            int u = tid + j * 256;
            if (u < TOT8) {
                int row = u >> 3, uu = u & 7;
                const uint4* src = (row < 128)
                    ? &Asrc[(size_t)(m0 + row) * KPU + k0u + uu]
                    : &Wsrc[(size_t)(n0 + row - 128) * KPU + k0u + uu];
                uint32_t dst = (row < 128)
                    ? sb0 + row * SKEW_B + uu * 16
                    : sb0 + BOFF + (row - 128) * SKEW_B + uu * 16;
                cpa16(dst, src);
            }
        }
        CP_COMMIT();
    };
    auto compute = [&](int st) {
        const uint32_t sb0 = st * STAGE;
        #pragma unroll
        for (int ks = 0; ks < 4; ks++) {
            const uint32_t ko = sb0 + ks * 32;
            uint32_t af[MI][4], bf[NI][2];
            #pragma unroll
            for (int p = 0; p < NI / 2; p++) {
                uint32_t r4[4];
                ldm_x4(r4, boff[p] + ko);
                bf[2 * p][0] = r4[0]; bf[2 * p + 1][0] = r4[1];
                bf[2 * p][1] = r4[2]; bf[2 * p + 1][1] = r4[3];
            }
            if (NI & 1) ldm_x2(bf[NI - 1], boff[NI / 2] + ko);
            #pragma unroll
            for (int mi = 0; mi < MI; mi++) ldm_x4(af[mi], aoff[mi] + ko);
            #pragma unroll
            for (int mi = 0; mi < MI; mi++)
                #pragma unroll
                for (int ni = 0; ni < NI; ni++)
                    mma16816(acc[mi][ni], af[mi], bf[ni]);
        }
    };

    issue_copy(0, 0);
    issue_copy(1, 1);
    for (int kc = 0; kc < NK; kc++) {
        if (kc + 1 < NK) { CP_WAIT(1); } else { CP_WAIT(0); }
        __syncthreads();
        if (kc + 2 < NK) issue_copy(kc + 2, (kc + 2) % STAGES);
        compute(kc % STAGES);
    }

    if (MODE == 2) {
        #pragma unroll
        for (int mi = 0; mi < MI; mi++) {
            #pragma unroll
            for (int ni = 0; ni < NI; ni++) {
                int r0 = m0 + wy * 64 + mi * 16 + gid;
                int c  = n0 + wx * 32 + ni * 8 + tig * 2;
                if (c < H2N) {
                    float bv0 = __ldg(&bias[c]), bv1 = __ldg(&bias[c + 1]);
                    #pragma unroll
                    for (int h = 0; h < 2; h++) {
                        int r = r0 + h * 8;
                        float v0 = acc[mi][ni][h * 2 + 0] + bv0;
                        float v1 = acc[mi][ni][h * 2 + 1] + bv1;
                        v0 = v0 > 0.f ? v0 : SLOPE * v0;
                        v1 = v1 > 0.f ? v1 : SLOPE * v1;
                        float h0 = __bfloat162float(__float2bfloat16(v0));
                        float h1 = __bfloat162float(__float2bfloat16(v1));
                        ((uint32_t*)g_A3h)[(size_t)r * 320 + (c >> 1)] = pk2(h0, h1);
                        ((uint32_t*)g_A3l)[(size_t)r * 320 + (c >> 1)] = pk2(v0 - h0, v1 - h1);
                    }
                }
            }
        }
    } else {
        __syncthreads();
        float* h3s = (float*)sm;             // [128][106]
        #pragma unroll
        for (int ni = 0; ni < NI; ni++) {
            int c = ni * 8 + tig * 2;
            float bv0 = (c < H3N) ? __ldg(&bias[c]) : 0.f;
            float bv1 = (c + 1 < H3N) ? __ldg(&bias[c + 1]) : 0.f;
            #pragma unroll
            for (int h = 0; h < 2; h++) {
                int r = wy * 16 + gid + h * 8;
                float v0 = fmaxf(acc[0][ni][h * 2 + 0] + bv0, 0.f);
                float v1 = fmaxf(acc[0][ni][h * 2 + 1] + bv1, 0.f);
                *(float2*)(&h3s[r * 106 + c]) = make_float2(v0, v1);
            }
        }
        __syncthreads();
        if (tid < 128) {
            const float* sW4 = (const float*)(sm + G3_W4);
            const float* sb4 = (const float*)(sm + G3_B4);
            int r = tid;
            float o[D_IN];
            #pragma unroll
            for (int oo = 0; oo < D_IN; oo++) o[oo] = sb4[oo];
            #pragma unroll 4
            for (int k = 0; k < H3N; k++) {
                float hv = h3s[r * 106 + k];
                #pragma unroll
                for (int oo = 0; oo < D_IN; oo++) o[oo] += hv * sW4[oo * H3N + k];
            }
            float s = 0.f;
            #pragma unroll
            for (int oo = 0; oo < D_IN; oo++) {
                o[oo] = o[oo] > 0.f ? o[oo] : SLOPE * o[oo];
                s += o[oo] * o[oo];
            }
            float inv = 1.f / fmaxf(sqrtf(s), EPS_F);
            float t[16];
            #pragma unroll
            for (int oo = 0; oo < 16; oo++) t[oo] = (oo < D_IN) ? o[oo] * inv : 0.f;
            union { uint4 q[6]; uint32_t u[24]; } out;
            #pragma unroll
            for (int oo = 0; oo < 16; oo += 2) {
                float ah = __bfloat162float(__float2bfloat16(t[oo]));
                float bh = __bfloat162float(__float2bfloat16(t[oo + 1]));
                out.u[oo / 2]      = pk2(ah, bh);
                out.u[8 + oo / 2]  = pk2(t[oo] - ah, t[oo + 1] - bh);
                out.u[16 + oo / 2] = pk2(ah, bh);
            }
            #pragma unroll
            for (int j = 0; j < 6; j++) g_t1s[(size_t)(m0 + r) * 6 + j] = out.q[j];
        }
    }
}

// ---------- similarity via split-bf16 mma ----------
#define SIM_SV  0
#define SIM_ST  196608
#define SIM_SMEM 208896
__global__ void __launch_bounds__(256, 1)
sim_kernel() {
    char* sm = dynsmem;
    char* sv  = sm + SIM_SV;    // [2048][96B]
    char* st1 = sm + SIM_ST;    // [128][96B]
    const int tid = threadIdx.x;
    const int wid = tid >> 5, lane = tid & 31;
    const int gid = lane >> 2, tig = lane & 3;
    const int wy = wid >> 2, wx = wid & 3;
    const int n0 = blockIdx.x * 128;

    for (int i = tid; i < B_ROWS * 6; i += 256) ((uint4*)sv)[i] = g_vns[i];
    for (int i = tid; i < 128 * 6; i += 256)   ((uint4*)st1)[i] = g_t1s[(size_t)n0 * 6 + i];
    __syncthreads();

    uint32_t bf[3][4][2];
    #pragma unroll
    for (int s = 0; s < 3; s++)
        #pragma unroll
        for (int ni = 0; ni < 4; ni++) {
            int n = wx * 32 + ni * 8 + gid;
            bf[s][ni][0] = *(const uint32_t*)(st1 + n * 96 + s * 32 + tig * 4);
            bf[s][ni][1] = *(const uint32_t*)(st1 + n * 96 + s * 32 + 16 + tig * 4);
        }

    for (int c = 0; c < 8; c++) {
        float acc[8][4][4];
        #pragma unroll
        for (int mi = 0; mi < 8; mi++)
            #pragma unroll
            for (int ni = 0; ni < 4; ni++)
                #pragma unroll
                for (int q = 0; q < 4; q++) acc[mi][ni][q] = 0.f;

        const char* va = sv + (c * 256 + wy * 128) * 96;
        #pragma unroll
        for (int s = 0; s < 3; s++) {
            #pragma unroll
            for (int mi = 0; mi < 8; mi++) {
                int r = mi * 16 + gid;
                uint32_t af[4];
                af[0] = *(const uint32_t*)(va + r * 96 + s * 32 + tig * 4);
                af[1] = *(const uint32_t*)(va + (r + 8) * 96 + s * 32 + tig * 4);
                af[2] = *(const uint32_t*)(va + r * 96 + s * 32 + 16 + tig * 4);
                af[3] = *(const uint32_t*)(va + (r + 8) * 96 + s * 32 + 16 + tig * 4);
                #pragma unroll
                for (int ni = 0; ni < 4; ni++)
                    mma16816(acc[mi][ni], af, bf[s][ni]);
            }
        }
        #pragma unroll
        for (int mi = 0; mi < 8; mi++) {
            #pragma unroll
            for (int h = 0; h < 2; h++) {
                float mx = -3.4e38f;
                #pragma unroll
                for (int ni = 0; ni < 4; ni++)
                    mx = fmaxf(mx, fmaxf(acc[mi][ni][h * 2], acc[mi][ni][h * 2 + 1]));
                mx = fmaxf(mx, __shfl_xor_sync(0xFFFFFFFF, mx, 1));
                mx = fmaxf(mx, __shfl_xor_sync(0xFFFFFFFF, mx, 2));
                if (tig == 0) {
                    int row = c * 256 + wy * 128 + mi * 16 + gid + 8 * h;
                    atomicMax(&g_umax[row], fkey(SCALE_F * mx));
                }
            }
        }
    }
}

__global__ void finish_kernel(float* __restrict__ out) {
    int t = blockIdx.x * blockDim.x + threadIdx.x;
    if (t < B_ROWS) out[t] = funkey(g_umax[t]);
}

// ================= host =================
extern "C" void kernel_launch(void* const* d_in, const int* in_sizes, int n_in,
                              void* d_out, int out_size) {
    const float *memx = 0, *value = 0, *W1 = 0, *b1 = 0, *W2 = 0, *b2 = 0,
                *W3 = 0, *b3 = 0, *W4 = 0, *b4 = 0;
    for (int i = 0; i < n_in; i++) {
        const float* p = (const float*)d_in[i];
        switch (in_sizes[i]) {
            case M_ROWS * D_IN: memx = p; break;
            case B_ROWS * D_IN: value = p; break;
            case H1N * D_IN:    W1 = p; break;
            case H1N:           b1 = p; break;
            case H2N * H1N:     W2 = p; break;
            case H2N:           b2 = p; break;
            case H3N * H2N:     W3 = p; break;
            case H3N:           b3 = p; break;
            case D_IN * H3N:    W4 = p; break;
            case D_IN:          b4 = p; break;
            default: break;
        }
    }

    cudaFuncSetAttribute(layer1_kernel, cudaFuncAttributeMaxDynamicSharedMemorySize, L1_SMEM);
    cudaFuncSetAttribute(gemm_kernel<2>, cudaFuncAttributeMaxDynamicSharedMemorySize, GEMM2_SMEM);
    cudaFuncSetAttribute(gemm_kernel<3>, cudaFuncAttributeMaxDynamicSharedMemorySize, G3_SMEM);
    cudaFuncSetAttribute(sim_kernel, cudaFuncAttributeMaxDynamicSharedMemorySize, SIM_SMEM);

    prep_w2<<<(640 * 40 + 255) / 256, 256>>>(W2);
    prep_w3<<<(128 * 80 + 255) / 256, 256>>>(W3);
    layer1_kernel<<<M_ROWS / 128, 256, L1_SMEM>>>(memx, W1, b1);
    gemm_kernel<2><<<dim3(M_ROWS / 128, 5), 256, GEMM2_SMEM>>>(b2, 0, 0);
    prep_vn_kernel<<<B_ROWS / 256, 256>>>(value);
    gemm_kernel<3><<<dim3(M_ROWS / 128, 1), 256, G3_SMEM>>>(b3, W4, b4);
    sim_kernel<<<M_ROWS / 128, 256, SIM_SMEM>>>();
    finish_kernel<<<B_ROWS / 256, 256>>>((float*)d_out);
}

// round 11
// speedup vs baseline: 4.5836x; 1.0009x over previous
#include <cuda_runtime.h>
#include <cuda_bf16.h>
#include <math.h>
#include <stdint.h>

#define M_ROWS 65536
#define B_ROWS 2048
#define D_IN   13
#define H1N    300
#define H2N    600
#define H3N    100
#define EPS_F  1e-8f
#define SCALE_F 23.0f
#define SLOPE  0.01f

extern __shared__ char dynsmem[];

// ============ scratch (device globals; no allocations) ============
__device__ uint4 g_A2h[65536ULL * 40];
__device__ uint4 g_A2l[65536ULL * 40];
__device__ uint4 g_A3h[65536ULL * 80];
__device__ uint4 g_A3l[65536ULL * 80];
__device__ uint4 g_W2h[640 * 40];
__device__ uint4 g_W2l[640 * 40];
__device__ uint4 g_W3h[128 * 80];
__device__ uint4 g_W3l[128 * 80];
__device__ uint4 g_vns[B_ROWS * 6];     // vn split: [vh|vh|vl], 48 bf16/row
__device__ uint4 g_t1s[65536ULL * 6];   // t1n split: [th|tl|th], 48 bf16/row
__device__ unsigned int g_umax[B_ROWS];

__device__ __forceinline__ unsigned fkey(float f) {
    unsigned b = __float_as_uint(f);
    return (b & 0x80000000u) ? ~b : (b | 0x80000000u);
}
__device__ __forceinline__ float funkey(unsigned u) {
    unsigned b = (u & 0x80000000u) ? (u ^ 0x80000000u) : ~u;
    return __uint_as_float(b);
}
__device__ __forceinline__ uint32_t pk2(float a, float b) {
    __nv_bfloat162 t = __floats2bfloat162_rn(a, b);
    return *reinterpret_cast<uint32_t*>(&t);
}
__device__ __forceinline__ uint32_t smem_u32(const void* p) {
    uint32_t a;
    asm("{ .reg .u64 t; cvta.to.shared.u64 t, %1; cvt.u32.u64 %0, t; }" : "=r"(a) : "l"(p));
    return a;
}
__device__ __forceinline__ void mma16816(float* d, const uint32_t* a, const uint32_t* b) {
    asm volatile(
        "mma.sync.aligned.m16n8k16.row.col.f32.bf16.bf16.f32 "
        "{%0,%1,%2,%3}, {%4,%5,%6,%7}, {%8,%9}, {%0,%1,%2,%3};"
        : "+f"(d[0]), "+f"(d[1]), "+f"(d[2]), "+f"(d[3])
        : "r"(a[0]), "r"(a[1]), "r"(a[2]), "r"(a[3]), "r"(b[0]), "r"(b[1]));
}
__device__ __forceinline__ void ldm_x4(uint32_t* r, uint32_t addr) {
    asm volatile("ldmatrix.sync.aligned.m8n8.x4.shared.b16 {%0,%1,%2,%3}, [%4];"
        : "=r"(r[0]), "=r"(r[1]), "=r"(r[2]), "=r"(r[3]) : "r"(addr));
}
__device__ __forceinline__ void ldm_x2(uint32_t* r, uint32_t addr) {
    asm volatile("ldmatrix.sync.aligned.m8n8.x2.shared.b16 {%0,%1}, [%2];"
        : "=r"(r[0]), "=r"(r[1]) : "r"(addr));
}
__device__ __forceinline__ void cpa16(uint32_t dst, const void* src) {
    asm volatile("cp.async.cg.shared.global [%0], [%1], 16;" :: "r"(dst), "l"(src));
}
#define CP_COMMIT() asm volatile("cp.async.commit_group;" ::: "memory")
#define CP_WAIT(n)  asm volatile("cp.async.wait_group %0;" :: "n"(n) : "memory")

// ---------- weight prep ----------
__global__ void prep_w2(const float* __restrict__ W2) {
    int e = blockIdx.x * 256 + threadIdx.x;       // [640][40] uint4
    if (e >= 640 * 40) return;
    int n = e / 40, c8 = e % 40;
    union { uint4 v; __nv_bfloat16 b[8]; } hu, lu;
    #pragma unroll
    for (int t = 0; t < 8; t++) {
        int k = c8 * 8 + t;
        float w = (n < H2N && k < H1N) ? W2[n * H1N + k] : 0.f;
        __nv_bfloat16 h = __float2bfloat16(w);
        hu.b[t] = h;
        lu.b[t] = __float2bfloat16(w - __bfloat162float(h));
    }
    g_W2h[e] = hu.v;
    g_W2l[e] = lu.v;
}
__global__ void prep_w3(const float* __restrict__ W3) {
    int e = blockIdx.x * 256 + threadIdx.x;       // [128][80] uint4
    if (e >= 128 * 80) return;
    int n = e / 80, c8 = e % 80;
    union { uint4 v; __nv_bfloat16 b[8]; } hu, lu;
    #pragma unroll
    for (int t = 0; t < 8; t++) {
        int k = c8 * 8 + t;
        float w = (n < H3N && k < H2N) ? W3[n * H2N + k] : 0.f;
        __nv_bfloat16 h = __float2bfloat16(w);
        hu.b[t] = h;
        lu.b[t] = __float2bfloat16(w - __bfloat162float(h));
    }
    g_W3h[e] = hu.v;
    g_W3l[e] = lu.v;
}

// ---------- prep vn ----------
__global__ void prep_vn_kernel(const float* __restrict__ value) {
    int t = blockIdx.x * blockDim.x + threadIdx.x;
    if (t >= B_ROWS) return;
    float v[16], s = 0.f;
    #pragma unroll
    for (int o = 0; o < 16; o++) v[o] = 0.f;
    #pragma unroll
    for (int o = 0; o < D_IN; o++) { v[o] = value[t * D_IN + o]; s += v[o] * v[o]; }
    float inv = 1.f / fmaxf(sqrtf(s), EPS_F);
    union { uint4 q[6]; uint32_t u[24]; } out;
    #pragma unroll
    for (int o = 0; o < 16; o += 2) {
        float a = v[o] * inv, b = v[o + 1] * inv;
        float ah = __bfloat162float(__float2bfloat16(a));
        float bh = __bfloat162float(__float2bfloat16(b));
        out.u[o / 2]      = pk2(ah, bh);
        out.u[8 + o / 2]  = pk2(ah, bh);
        out.u[16 + o / 2] = pk2(a - ah, b - bh);
    }
    #pragma unroll
    for (int j = 0; j < 6; j++) g_vns[t * 6 + j] = out.q[j];
    g_umax[t] = 0u;
}

// ---------- layer 1 ----------
#define L1_SW   0
#define L1_SB   20480
#define L1_SX   21760
#define L1_SMEM 32000
__global__ void __launch_bounds__(256)
layer1_kernel(const float* __restrict__ memx, const float* __restrict__ W1,
              const float* __restrict__ b1) {
    float* sW = (float*)(dynsmem + L1_SW);   // [320][16]
    float* sb = (float*)(dynsmem + L1_SB);   // [320]
    float* sx = (float*)(dynsmem + L1_SX);   // [128][20]
    const int tid = threadIdx.x;
    const int m0 = blockIdx.x * 128;
    const int row = tid & 127, half = tid >> 7;

    for (int i = tid; i < 320 * 16; i += 256) sW[i] = 0.f;
    for (int i = tid; i < 320; i += 256) sb[i] = (i < H1N) ? b1[i] : 0.f;
    for (int i = tid; i < 128 * 20; i += 256) sx[i] = 0.f;
    __syncthreads();
    for (int i = tid; i < H1N * D_IN; i += 256) sW[(i / D_IN) * 16 + (i % D_IN)] = W1[i];
    for (int i = tid; i < 128 * D_IN; i += 256) sx[(i / D_IN) * 20 + (i % D_IN)] = memx[(size_t)m0 * D_IN + i];
    __syncthreads();

    float4 xv[4];
    #pragma unroll
    for (int j = 0; j < 4; j++) xv[j] = *(float4*)(&sx[row * 20 + 4 * j]);

    const size_t rbase = (size_t)(m0 + row) * 40 + half * 20;
    #pragma unroll 1
    for (int gg = 0; gg < 10; gg++) {
        uint4 hq[2], lq[2];
        #pragma unroll
        for (int g2 = 0; g2 < 2; g2++) {
            union { uint4 v; uint32_t u[4]; } hv, lv;
            #pragma unroll
            for (int p = 0; p < 4; p++) {
                float o2[2];
                #pragma unroll
                for (int e = 0; e < 2; e++) {
                    int c = (half * 20 + gg * 2 + g2) * 8 + p * 2 + e;
                    float acc = sb[c];
                    #pragma unroll
                    for (int j = 0; j < 4; j++) {
                        float4 w = *(float4*)(&sW[c * 16 + 4 * j]);
                        acc += xv[j].x * w.x + xv[j].y * w.y + xv[j].z * w.z + xv[j].w * w.w;
                    }
                    o2[e] = fmaxf(acc, 0.f);
                }
                float h0 = __bfloat162float(__float2bfloat16(o2[0]));
                float h1 = __bfloat162float(__float2bfloat16(o2[1]));
                hv.u[p] = pk2(h0, h1);
                lv.u[p] = pk2(o2[0] - h0, o2[1] - h1);
            }
            hq[g2] = hv.v; lq[g2] = lv.v;
        }
        g_A2h[rbase + gg * 2] = hq[0];
        g_A2h[rbase + gg * 2 + 1] = hq[1];
        g_A2l[rbase + gg * 2] = lq[0];
        g_A2l[rbase + gg * 2 + 1] = lq[1];
    }
}

// ---------- bf16 mma GEMM: cp.async 3-stage + ldmatrix + reg double-buffer ----------
#define SKEW_B 144
#define STAGES 3
#define G2_STAGE (256 * SKEW_B)
#define G3_STAGE (232 * SKEW_B)
#define GEMM2_SMEM (STAGES * G2_STAGE)                // 110592
#define G3_W4   (STAGES * G3_STAGE)
#define G3_B4   (G3_W4 + 5200)
#define G3_SMEM (G3_B4 + 64)                          // 105488
template<int MODE>
__global__ void __launch_bounds__(256, 2)
gemm_kernel(const float* __restrict__ bias,
            const float* __restrict__ W4, const float* __restrict__ b4) {
    constexpr int KPU = (MODE == 2) ? 40 : 80;
    constexpr int SEC = (MODE == 2) ? 5 : 10;
    constexpr int NK  = 3 * SEC;
    constexpr int NB  = (MODE == 2) ? 128 : 104;
    constexpr int MI  = (MODE == 2) ? 4 : 1;
    constexpr int NI  = (MODE == 2) ? 4 : 13;
    constexpr int STAGE = (MODE == 2) ? G2_STAGE : G3_STAGE;
    constexpr int BOFF = 128 * SKEW_B;
    char* sm = dynsmem;
    const uint32_t smb = smem_u32(sm);

    const int tid = threadIdx.x;
    const int wid = tid >> 5, lane = tid & 31;
    const int gid = lane >> 2, tig = lane & 3;
    const int wy = (MODE == 2) ? (wid >> 2) : wid;
    const int wx = (MODE == 2) ? (wid & 3) : 0;
    const int m0 = blockIdx.x * 128;
    const int n0 = blockIdx.y * ((MODE == 2) ? 128 : 104);

    if (MODE == 3) {
        float* sW4 = (float*)(sm + G3_W4);
        float* sb4 = (float*)(sm + G3_B4);
        for (int i = tid; i < D_IN * H3N; i += 256) sW4[i] = W4[i];
        if (tid < D_IN) sb4[tid] = b4[tid];
    }

    float acc[MI][NI][4];
    #pragma unroll
    for (int mi = 0; mi < MI; mi++)
        #pragma unroll
        for (int ni = 0; ni < NI; ni++)
            #pragma unroll
            for (int q = 0; q < 4; q++) acc[mi][ni][q] = 0.f;

    const int lrow = lane & 15, lkh = lane >> 4;
    uint32_t aoff[MI], boff[(NI + 1) / 2];
    #pragma unroll
    for (int mi = 0; mi < MI; mi++) {
        int r = ((MODE == 2) ? (wy * 64 + mi * 16) : (wy * 16)) + lrow;
        aoff[mi] = smb + r * SKEW_B + lkh * 16;
    }
    #pragma unroll
    for (int p = 0; p < (NI + 1) / 2; p++) {
        int nb = wx * 32 + p * 16;
        if (2 * p + 1 < NI || MODE == 2) {
            boff[p] = smb + BOFF + (nb + lrow) * SKEW_B + lkh * 16;
        } else {
            int l16 = lane & 15;
            boff[p] = smb + BOFF + (96 + (l16 & 7)) * SKEW_B + (l16 >> 3) * 16;
        }
    }

    constexpr int TOT8 = (128 + NB) * 8;
    constexpr int NLD = (TOT8 + 255) / 256;
    auto issue_copy = [&](int kc, int st) {
        int sec = kc / SEC, idx = kc % SEC;
        const uint4* Asrc = (MODE == 2) ? ((sec < 2) ? g_A2h : g_A2l)
                                        : ((sec < 2) ? g_A3h : g_A3l);
        const uint4* Wsrc = (MODE == 2) ? ((sec == 1) ? g_W2l : g_W2h)
                                        : ((sec == 1) ? g_W3l : g_W3h);
        int k0u = idx * 8;
        uint32_t sb0 = smb + st * STAGE;
        #pragma unroll
        for (int j = 0; j < NLD; j++) {
            int u = tid + j * 256;
            if (u < TOT8) {
                int row = u >> 3, uu = u & 7;
                const uint4* src = (row < 128)
                    ? &Asrc[(size_t)(m0 + row) * KPU + k0u + uu]
                    : &Wsrc[(size_t)(n0 + row - 128) * KPU + k0u + uu];
                uint32_t dst = (row < 128)
                    ? sb0 + row * SKEW_B + uu * 16
                    : sb0 + BOFF + (row - 128) * SKEW_B + uu * 16;
                cpa16(dst, src);
            }
        }
        CP_COMMIT();
    };

    auto load_af = [&](uint32_t ko, uint32_t (&af)[MI][4]) {
        #pragma unroll
        for (int mi = 0; mi < MI; mi++) ldm_x4(af[mi], aoff[mi] + ko);
    };
    auto load_bf = [&](uint32_t ko, uint32_t (&bf)[NI][2]) {
        #pragma unroll
        for (int p = 0; p < NI / 2; p++) {
            uint32_t r4[4];
            ldm_x4(r4, boff[p] + ko);
            bf[2 * p][0] = r4[0]; bf[2 * p + 1][0] = r4[1];
            bf[2 * p][1] = r4[2]; bf[2 * p + 1][1] = r4[3];
        }
        if (NI & 1) ldm_x2(bf[NI - 1], boff[NI / 2] + ko);
    };
    auto do_mma = [&](uint32_t (&af)[MI][4], uint32_t (&bf)[NI][2]) {
        #pragma unroll
        for (int mi = 0; mi < MI; mi++)
            #pragma unroll
            for (int ni = 0; ni < NI; ni++)
                mma16816(acc[mi][ni], af[mi], bf[ni]);
    };

    auto compute = [&](int st) {
        const uint32_t sb0 = st * STAGE;
        uint32_t af[2][MI][4];
        if (MODE == 2) {
            uint32_t bf[2][NI][2];
            load_bf(sb0, bf[0]);
            load_af(sb0, af[0]);
            #pragma unroll
            for (int ks = 0; ks < 4; ks++) {
                int cur = ks & 1, nxt = cur ^ 1;
                if (ks < 3) {
                    load_bf(sb0 + (ks + 1) * 32, bf[nxt]);
                    load_af(sb0 + (ks + 1) * 32, af[nxt]);
                }
                do_mma(af[cur], bf[cur]);
            }
        } else {
            uint32_t bf[NI][2];
            load_af(sb0, af[0]);
            #pragma unroll
            for (int ks = 0; ks < 4; ks++) {
                int cur = ks & 1, nxt = cur ^ 1;
                if (ks < 3) load_af(sb0 + (ks + 1) * 32, af[nxt]);
                load_bf(sb0 + ks * 32, bf);
                do_mma(af[cur], bf);
            }
        }
    };

    issue_copy(0, 0);
    issue_copy(1, 1);
    for (int kc = 0; kc < NK; kc++) {
        if (kc + 1 < NK) { CP_WAIT(1); } else { CP_WAIT(0); }
        __syncthreads();
        if (kc + 2 < NK) issue_copy(kc + 2, (kc + 2) % STAGES);
        compute(kc % STAGES);
    }

    if (MODE == 2) {
        #pragma unroll
        for (int mi = 0; mi < MI; mi++) {
            #pragma unroll
            for (int ni = 0; ni < NI; ni++) {
                int r0 = m0 + wy * 64 + mi * 16 + gid;
                int c  = n0 + wx * 32 + ni * 8 + tig * 2;
                if (c < H2N) {
                    float bv0 = __ldg(&bias[c]), bv1 = __ldg(&bias[c + 1]);
                    #pragma unroll
                    for (int h = 0; h < 2; h++) {
                        int r = r0 + h * 8;
                        float v0 = acc[mi][ni][h * 2 + 0] + bv0;
                        float v1 = acc[mi][ni][h * 2 + 1] + bv1;
                        v0 = v0 > 0.f ? v0 : SLOPE * v0;
                        v1 = v1 > 0.f ? v1 : SLOPE * v1;
                        float h0 = __bfloat162float(__float2bfloat16(v0));
                        float h1 = __bfloat162float(__float2bfloat16(v1));
                        ((uint32_t*)g_A3h)[(size_t)r * 320 + (c >> 1)] = pk2(h0, h1);
                        ((uint32_t*)g_A3l)[(size_t)r * 320 + (c >> 1)] = pk2(v0 - h0, v1 - h1);
                    }
                }
            }
        }
    } else {
        __syncthreads();
        float* h3s = (float*)sm;             // [128][106]
        #pragma unroll
        for (int ni = 0; ni < NI; ni++) {
            int c = ni * 8 + tig * 2;
            float bv0 = (c < H3N) ? __ldg(&bias[c]) : 0.f;
            float bv1 = (c + 1 < H3N) ? __ldg(&bias[c + 1]) : 0.f;
            #pragma unroll
            for (int h = 0; h < 2; h++) {
                int r = wy * 16 + gid + h * 8;
                float v0 = fmaxf(acc[0][ni][h * 2 + 0] + bv0, 0.f);
                float v1 = fmaxf(acc[0][ni][h * 2 + 1] + bv1, 0.f);
                *(float2*)(&h3s[r * 106 + c]) = make_float2(v0, v1);
            }
        }
        __syncthreads();
        if (tid < 128) {
            const float* sW4 = (const float*)(sm + G3_W4);
            const float* sb4 = (const float*)(sm + G3_B4);
            int r = tid;
            float o[D_IN];
            #pragma unroll
            for (int oo = 0; oo < D_IN; oo++) o[oo] = sb4[oo];
            #pragma unroll 4
            for (int k = 0; k < H3N; k++) {
                float hv = h3s[r * 106 + k];
                #pragma unroll
                for (int oo = 0; oo < D_IN; oo++) o[oo] += hv * sW4[oo * H3N + k];
            }
            float s = 0.f;
            #pragma unroll
            for (int oo = 0; oo < D_IN; oo++) {
                o[oo] = o[oo] > 0.f ? o[oo] : SLOPE * o[oo];
                s += o[oo] * o[oo];
            }
            float inv = 1.f / fmaxf(sqrtf(s), EPS_F);
            float t[16];
            #pragma unroll
            for (int oo = 0; oo < 16; oo++) t[oo] = (oo < D_IN) ? o[oo] * inv : 0.f;
            union { uint4 q[6]; uint32_t u[24]; } out;
            #pragma unroll
            for (int oo = 0; oo < 16; oo += 2) {
                float ah = __bfloat162float(__float2bfloat16(t[oo]));
                float bh = __bfloat162float(__float2bfloat16(t[oo + 1]));
                out.u[oo / 2]      = pk2(ah, bh);
                out.u[8 + oo / 2]  = pk2(t[oo] - ah, t[oo + 1] - bh);
                out.u[16 + oo / 2] = pk2(ah, bh);
            }
            #pragma unroll
            for (int j = 0; j < 6; j++) g_t1s[(size_t)(m0 + r) * 6 + j] = out.q[j];
        }
    }
}

// ---------- similarity via split-bf16 mma ----------
#define SIM_SV  0
#define SIM_ST  196608
#define SIM_SMEM 208896
__global__ void __launch_bounds__(256, 1)
sim_kernel() {
    char* sm = dynsmem;
    char* sv  = sm + SIM_SV;    // [2048][96B]
    char* st1 = sm + SIM_ST;    // [128][96B]
    const int tid = threadIdx.x;
    const int wid = tid >> 5, lane = tid & 31;
    const int gid = lane >> 2, tig = lane & 3;
    const int wy = wid >> 2, wx = wid & 3;
    const int n0 = blockIdx.x * 128;

    for (int i = tid; i < B_ROWS * 6; i += 256) ((uint4*)sv)[i] = g_vns[i];
    for (int i = tid; i < 128 * 6; i += 256)   ((uint4*)st1)[i] = g_t1s[(size_t)n0 * 6 + i];
    __syncthreads();

    uint32_t bf[3][4][2];
    #pragma unroll
    for (int s = 0; s < 3; s++)
        #pragma unroll
        for (int ni = 0; ni < 4; ni++) {
            int n = wx * 32 + ni * 8 + gid;
            bf[s][ni][0] = *(const uint32_t*)(st1 + n * 96 + s * 32 + tig * 4);
            bf[s][ni][1] = *(const uint32_t*)(st1 + n * 96 + s * 32 + 16 + tig * 4);
        }

    for (int c = 0; c < 8; c++) {
        float acc[8][4][4];
        #pragma unroll
        for (int mi = 0; mi < 8; mi++)
            #pragma unroll
            for (int ni = 0; ni < 4; ni++)
                #pragma unroll
                for (int q = 0; q < 4; q++) acc[mi][ni][q] = 0.f;

        const char* va = sv + (c * 256 + wy * 128) * 96;
        #pragma unroll
        for (int s = 0; s < 3; s++) {
            #pragma unroll
            for (int mi = 0; mi < 8; mi++) {
                int r = mi * 16 + gid;
                uint32_t af[4];
                af[0] = *(const uint32_t*)(va + r * 96 + s * 32 + tig * 4);
                af[1] = *(const uint32_t*)(va + (r + 8) * 96 + s * 32 + tig * 4);
                af[2] = *(const uint32_t*)(va + r * 96 + s * 32 + 16 + tig * 4);
                af[3] = *(const uint32_t*)(va + (r + 8) * 96 + s * 32 + 16 + tig * 4);
                #pragma unroll
                for (int ni = 0; ni < 4; ni++)
                    mma16816(acc[mi][ni], af, bf[s][ni]);
            }
        }
        #pragma unroll
        for (int mi = 0; mi < 8; mi++) {
            #pragma unroll
            for (int h = 0; h < 2; h++) {
                float mx = -3.4e38f;
                #pragma unroll
                for (int ni = 0; ni < 4; ni++)
                    mx = fmaxf(mx, fmaxf(acc[mi][ni][h * 2], acc[mi][ni][h * 2 + 1]));
                mx = fmaxf(mx, __shfl_xor_sync(0xFFFFFFFF, mx, 1));
                mx = fmaxf(mx, __shfl_xor_sync(0xFFFFFFFF, mx, 2));
                if (tig == 0) {
                    int row = c * 256 + wy * 128 + mi * 16 + gid + 8 * h;
                    atomicMax(&g_umax[row], fkey(SCALE_F * mx));
                }
            }
        }
    }
}

__global__ void finish_kernel(float* __restrict__ out) {
    int t = blockIdx.x * blockDim.x + threadIdx.x;
    if (t < B_ROWS) out[t] = funkey(g_umax[t]);
}

// ================= host =================
extern "C" void kernel_launch(void* const* d_in, const int* in_sizes, int n_in,
                              void* d_out, int out_size) {
    const float *memx = 0, *value = 0, *W1 = 0, *b1 = 0, *W2 = 0, *b2 = 0,
                *W3 = 0, *b3 = 0, *W4 = 0, *b4 = 0;
    for (int i = 0; i < n_in; i++) {
        const float* p = (const float*)d_in[i];
        switch (in_sizes[i]) {
            case M_ROWS * D_IN: memx = p; break;
            case B_ROWS * D_IN: value = p; break;
            case H1N * D_IN:    W1 = p; break;
            case H1N:           b1 = p; break;
            case H2N * H1N:     W2 = p; break;
            case H2N:           b2 = p; break;
            case H3N * H2N:     W3 = p; break;
            case H3N:           b3 = p; break;
            case D_IN * H3N:    W4 = p; break;
            case D_IN:          b4 = p; break;
            default: break;
        }
    }

    cudaFuncSetAttribute(layer1_kernel, cudaFuncAttributeMaxDynamicSharedMemorySize, L1_SMEM);
    cudaFuncSetAttribute(gemm_kernel<2>, cudaFuncAttributeMaxDynamicSharedMemorySize, GEMM2_SMEM);
    cudaFuncSetAttribute(gemm_kernel<3>, cudaFuncAttributeMaxDynamicSharedMemorySize, G3_SMEM);
    cudaFuncSetAttribute(sim_kernel, cudaFuncAttributeMaxDynamicSharedMemorySize, SIM_SMEM);

    prep_w2<<<(640 * 40 + 255) / 256, 256>>>(W2);
    prep_w3<<<(128 * 80 + 255) / 256, 256>>>(W3);
    layer1_kernel<<<M_ROWS / 128, 256, L1_SMEM>>>(memx, W1, b1);
    gemm_kernel<2><<<dim3(M_ROWS / 128, 5), 256, GEMM2_SMEM>>>(b2, 0, 0);
    prep_vn_kernel<<<B_ROWS / 256, 256>>>(value);
    gemm_kernel<3><<<dim3(M_ROWS / 128, 1), 256, G3_SMEM>>>(b3, W4, b4);
    sim_kernel<<<M_ROWS / 128, 256, SIM_SMEM>>>();
    finish_kernel<<<B_ROWS / 256, 256>>>((float*)d_out);
}